// round 1
// baseline (speedup 1.0000x reference)
#include <cuda_runtime.h>
#include <math.h>

#define T_TOK 4096
#define HID   2048
#define INTERD 10944
#define EPS 1e-6f

#define BM 128
#define BN 64
#define BK 16

// ---------------- scratch (device globals: allocation-free rule) ----------------
__device__ float g_hnorm [(size_t)T_TOK * HID];
__device__ float g_q     [(size_t)T_TOK * HID];
__device__ float g_hidden[(size_t)T_TOK * HID];
__device__ float g_hpost [(size_t)T_TOK * HID];
__device__ float g_act   [(size_t)T_TOK * INTERD];

// ---------------- RMSNorm: one block per row (2048 floats) ----------------
__global__ __launch_bounds__(256) void rmsnorm_kernel(
    const float* __restrict__ x, const float* __restrict__ w, float* __restrict__ out)
{
    long row = blockIdx.x;
    const float4* xr = (const float4*)(x + row * (long)HID);
    const float4* wr = (const float4*)w;
    float4*       orow = (float4*)(out + row * (long)HID);
    int tid = threadIdx.x;

    float4 v0 = xr[tid];
    float4 v1 = xr[tid + 256];
    float ss = v0.x*v0.x + v0.y*v0.y + v0.z*v0.z + v0.w*v0.w
             + v1.x*v1.x + v1.y*v1.y + v1.z*v1.z + v1.w*v1.w;

    #pragma unroll
    for (int off = 16; off > 0; off >>= 1)
        ss += __shfl_xor_sync(0xffffffffu, ss, off);

    __shared__ float warp_ss[8];
    __shared__ float s_scale;
    int lane = tid & 31, wid = tid >> 5;
    if (lane == 0) warp_ss[wid] = ss;
    __syncthreads();
    if (tid == 0) {
        float tot = 0.f;
        #pragma unroll
        for (int i = 0; i < 8; i++) tot += warp_ss[i];
        s_scale = rsqrtf(tot / (float)HID + EPS);
    }
    __syncthreads();
    float scale = s_scale;

    float4 w0 = wr[tid];
    float4 w1 = wr[tid + 256];
    float4 o0, o1;
    o0.x = v0.x * scale * w0.x; o0.y = v0.y * scale * w0.y;
    o0.z = v0.z * scale * w0.z; o0.w = v0.w * scale * w0.w;
    o1.x = v1.x * scale * w1.x; o1.y = v1.y * scale * w1.y;
    o1.z = v1.z * scale * w1.z; o1.w = v1.w * scale * w1.w;
    orow[tid]       = o0;
    orow[tid + 256] = o1;
}

// ---------------- GEMM: C[M,N] = A[M,K] @ W[N,K]^T (+ optional residual) ----------------
// BM=128, BN=64, BK=16, 256 threads, 8x4 per-thread tile.
template<int MODE>  // 0: plain, 1: C = R + A@W^T
__global__ __launch_bounds__(256) void gemm_tn(
    const float* __restrict__ A, const float* __restrict__ W,
    const float* __restrict__ R, float* __restrict__ C,
    int M, int N, int K)
{
    __shared__ float As[BK][BM];
    __shared__ float Ws[BK][BN];

    int tid = threadIdx.x;
    int tx = tid & 15;   // N direction (16 threads * 4 cols)
    int ty = tid >> 4;   // M direction (16 threads * 8 rows)
    long row0 = (long)blockIdx.y * BM;
    long col0 = (long)blockIdx.x * BN;
    const float* Ab = A + row0 * K;
    const float* Wb = W + col0 * K;

    float acc[8][4];
    #pragma unroll
    for (int i = 0; i < 8; i++)
        #pragma unroll
        for (int j = 0; j < 4; j++) acc[i][j] = 0.f;

    int lr = tid >> 2;        // 0..63
    int lk = (tid & 3) * 4;   // 0,4,8,12

    for (int kt = 0; kt < K; kt += BK) {
        // load A tile (128x16) transposed into As[k][m]
        #pragma unroll
        for (int it = 0; it < 2; it++) {
            int r = lr + it * 64;
            float4 v = *(const float4*)(Ab + (long)r * K + kt + lk);
            As[lk + 0][r] = v.x; As[lk + 1][r] = v.y;
            As[lk + 2][r] = v.z; As[lk + 3][r] = v.w;
        }
        // load W tile (64x16) transposed into Ws[k][n]
        {
            float4 v = *(const float4*)(Wb + (long)lr * K + kt + lk);
            Ws[lk + 0][lr] = v.x; Ws[lk + 1][lr] = v.y;
            Ws[lk + 2][lr] = v.z; Ws[lk + 3][lr] = v.w;
        }
        __syncthreads();

        #pragma unroll
        for (int k = 0; k < BK; k++) {
            float4 a0 = *(const float4*)&As[k][ty * 8];
            float4 a1 = *(const float4*)&As[k][ty * 8 + 4];
            float4 b  = *(const float4*)&Ws[k][tx * 4];
            float av[8] = {a0.x, a0.y, a0.z, a0.w, a1.x, a1.y, a1.z, a1.w};
            float bv[4] = {b.x, b.y, b.z, b.w};
            #pragma unroll
            for (int i = 0; i < 8; i++)
                #pragma unroll
                for (int j = 0; j < 4; j++)
                    acc[i][j] += av[i] * bv[j];
        }
        __syncthreads();
    }

    #pragma unroll
    for (int i = 0; i < 8; i++) {
        long r = row0 + ty * 8 + i;
        #pragma unroll
        for (int j = 0; j < 4; j++) {
            long c = col0 + tx * 4 + j;
            long idx = r * (long)N + c;
            float v = acc[i][j];
            if (MODE == 1) v += R[idx];
            C[idx] = v;
        }
    }
}

// ---------------- fused gate/up GEMM: C = silu(A@Wg^T) * (A@Wu^T) ----------------
__global__ __launch_bounds__(256) void gemm_gateup(
    const float* __restrict__ A, const float* __restrict__ Wg,
    const float* __restrict__ Wu, float* __restrict__ C,
    int M, int N, int K)
{
    __shared__ float As[BK][BM];
    __shared__ float Gs[BK][BN];
    __shared__ float Us[BK][BN];

    int tid = threadIdx.x;
    int tx = tid & 15;
    int ty = tid >> 4;
    long row0 = (long)blockIdx.y * BM;
    long col0 = (long)blockIdx.x * BN;
    const float* Ab = A + row0 * K;
    const float* Gb = Wg + col0 * K;
    const float* Ub = Wu + col0 * K;

    float accg[8][4], accu[8][4];
    #pragma unroll
    for (int i = 0; i < 8; i++)
        #pragma unroll
        for (int j = 0; j < 4; j++) { accg[i][j] = 0.f; accu[i][j] = 0.f; }

    int lr = tid >> 2;
    int lk = (tid & 3) * 4;

    for (int kt = 0; kt < K; kt += BK) {
        #pragma unroll
        for (int it = 0; it < 2; it++) {
            int r = lr + it * 64;
            float4 v = *(const float4*)(Ab + (long)r * K + kt + lk);
            As[lk + 0][r] = v.x; As[lk + 1][r] = v.y;
            As[lk + 2][r] = v.z; As[lk + 3][r] = v.w;
        }
        {
            float4 v = *(const float4*)(Gb + (long)lr * K + kt + lk);
            Gs[lk + 0][lr] = v.x; Gs[lk + 1][lr] = v.y;
            Gs[lk + 2][lr] = v.z; Gs[lk + 3][lr] = v.w;
            float4 u = *(const float4*)(Ub + (long)lr * K + kt + lk);
            Us[lk + 0][lr] = u.x; Us[lk + 1][lr] = u.y;
            Us[lk + 2][lr] = u.z; Us[lk + 3][lr] = u.w;
        }
        __syncthreads();

        #pragma unroll
        for (int k = 0; k < BK; k++) {
            float4 a0 = *(const float4*)&As[k][ty * 8];
            float4 a1 = *(const float4*)&As[k][ty * 8 + 4];
            float4 bg = *(const float4*)&Gs[k][tx * 4];
            float4 bu = *(const float4*)&Us[k][tx * 4];
            float av[8] = {a0.x, a0.y, a0.z, a0.w, a1.x, a1.y, a1.z, a1.w};
            float gv[4] = {bg.x, bg.y, bg.z, bg.w};
            float uv[4] = {bu.x, bu.y, bu.z, bu.w};
            #pragma unroll
            for (int i = 0; i < 8; i++) {
                #pragma unroll
                for (int j = 0; j < 4; j++) {
                    accg[i][j] += av[i] * gv[j];
                    accu[i][j] += av[i] * uv[j];
                }
            }
        }
        __syncthreads();
    }

    #pragma unroll
    for (int i = 0; i < 8; i++) {
        long r = row0 + ty * 8 + i;
        #pragma unroll
        for (int j = 0; j < 4; j++) {
            long c = col0 + tx * 4 + j;
            float g = accg[i][j];
            float s = g / (1.f + expf(-g));
            C[r * (long)N + c] = s * accu[i][j];
        }
    }
}

// ---------------- launch ----------------
extern "C" void kernel_launch(void* const* d_in, const int* in_sizes, int n_in,
                              void* d_out, int out_size)
{
    const float* x      = (const float*)d_in[0];
    // d_in[1] = positions (unused)
    const float* in_w   = (const float*)d_in[2];
    const float* post_w = (const float*)d_in[3];
    const float* Wq     = (const float*)d_in[4];
    const float* Wo     = (const float*)d_in[5];
    const float* Wg     = (const float*)d_in[6];
    const float* Wu     = (const float*)d_in[7];
    const float* Wd     = (const float*)d_in[8];
    float* out = (float*)d_out;

    float *hnorm, *q, *hidden, *hpost, *act;
    cudaGetSymbolAddress((void**)&hnorm,  g_hnorm);
    cudaGetSymbolAddress((void**)&q,      g_q);
    cudaGetSymbolAddress((void**)&hidden, g_hidden);
    cudaGetSymbolAddress((void**)&hpost,  g_hpost);
    cudaGetSymbolAddress((void**)&act,    g_act);

    // 1. h_norm = rmsnorm(x) * in_w
    rmsnorm_kernel<<<T_TOK, 256>>>(x, in_w, hnorm);

    // 2. q = h_norm @ Wq^T
    gemm_tn<0><<<dim3(HID / BN, T_TOK / BM), 256>>>(hnorm, Wq, nullptr, q, T_TOK, HID, HID);

    // 3. hidden = x + q @ Wo^T
    gemm_tn<1><<<dim3(HID / BN, T_TOK / BM), 256>>>(q, Wo, x, hidden, T_TOK, HID, HID);

    // 4. h_post = rmsnorm(hidden) * post_w
    rmsnorm_kernel<<<T_TOK, 256>>>(hidden, post_w, hpost);

    // 5. act = silu(h_post @ Wg^T) * (h_post @ Wu^T)
    gemm_gateup<<<dim3(INTERD / BN, T_TOK / BM), 256>>>(hpost, Wg, Wu, act, T_TOK, INTERD, HID);

    // 6. out = hidden + act @ Wd^T
    gemm_tn<1><<<dim3(HID / BN, T_TOK / BM), 256>>>(act, Wd, hidden, out, T_TOK, HID, INTERD);
}

// round 4
// speedup vs baseline: 3.7010x; 3.7010x over previous
#include <cuda_runtime.h>
#include <cstdint>
#include <math.h>

#define T_TOK  4096
#define HID    2048
#define INTERD 10944
#define EPS    1e-6f

#define BK 32
#define STAGES 4
#define A_TILE_B 16384                 // 128 rows * 128B
#define B_TILE_B 16384                 // 128 rows * 128B (plain) / 2x64 rows (gateup)
#define STAGE_B  (A_TILE_B + B_TILE_B) // 32768
#define SMEM_TOTAL (STAGES * STAGE_B)  // 131072

// ---------------- scratch (device globals; allocation-free rule) ----------------
__device__ float g_hnorm [(size_t)T_TOK * HID];
__device__ float g_q     [(size_t)T_TOK * HID];
__device__ float g_hidden[(size_t)T_TOK * HID];
__device__ float g_hpost [(size_t)T_TOK * HID];
__device__ float g_act   [(size_t)T_TOK * INTERD];
__device__ float g_tWq   [(size_t)HID * HID];
__device__ float g_tWo   [(size_t)HID * HID];
__device__ float g_tWg   [(size_t)INTERD * HID];
__device__ float g_tWu   [(size_t)INTERD * HID];
__device__ float g_tWd   [(size_t)HID * INTERD];

// ---------------- PTX helpers ----------------
static __device__ __forceinline__ uint32_t s2u(const void* p) {
    uint32_t a;
    asm("{ .reg .u64 t; cvta.to.shared.u64 t, %1; cvt.u32.u64 %0, t; }" : "=r"(a) : "l"(p));
    return a;
}
static __device__ __forceinline__ float rna_tf32(float x) {
    uint32_t u;
    asm("cvt.rna.tf32.f32 %0, %1;" : "=r"(u) : "f"(x));
    return __uint_as_float(u);
}
static __device__ __forceinline__ void cpa16(uint32_t s, const void* g) {
    asm volatile("cp.async.cg.shared.global [%0], [%1], 16;" :: "r"(s), "l"(g));
}
static __device__ __forceinline__ void ldsm4(uint32_t& r0, uint32_t& r1,
                                             uint32_t& r2, uint32_t& r3, uint32_t addr) {
    asm volatile("ldmatrix.sync.aligned.m8n8.x4.shared.b16 {%0,%1,%2,%3}, [%4];"
                 : "=r"(r0), "=r"(r1), "=r"(r2), "=r"(r3) : "r"(addr));
}
static __device__ __forceinline__ void mma_tf32(float* c, const uint32_t* a,
                                                uint32_t b0, uint32_t b1) {
    asm volatile(
        "mma.sync.aligned.m16n8k8.row.col.f32.tf32.tf32.f32 "
        "{%0,%1,%2,%3}, {%4,%5,%6,%7}, {%8,%9}, {%0,%1,%2,%3};"
        : "+f"(c[0]), "+f"(c[1]), "+f"(c[2]), "+f"(c[3])
        : "r"(a[0]), "r"(a[1]), "r"(a[2]), "r"(a[3]), "r"(b0), "r"(b1));
}
static __device__ __forceinline__ uint32_t sw128(uint32_t off) {
    return off ^ ((off >> 3) & 0x70);
}

// ---------------- RMSNorm (fp32 in, tf32-RNE out) ----------------
__global__ __launch_bounds__(256) void rmsnorm_kernel(
    const float* __restrict__ x, const float* __restrict__ w, float* __restrict__ out)
{
    long row = blockIdx.x;
    const float4* xr = (const float4*)(x + row * (long)HID);
    const float4* wr = (const float4*)w;
    float4* orow = (float4*)(out + row * (long)HID);
    int tid = threadIdx.x;

    float4 v0 = xr[tid];
    float4 v1 = xr[tid + 256];
    float ss = v0.x*v0.x + v0.y*v0.y + v0.z*v0.z + v0.w*v0.w
             + v1.x*v1.x + v1.y*v1.y + v1.z*v1.z + v1.w*v1.w;

    #pragma unroll
    for (int off = 16; off > 0; off >>= 1)
        ss += __shfl_xor_sync(0xffffffffu, ss, off);

    __shared__ float warp_ss[8];
    __shared__ float s_scale;
    int lane = tid & 31, wid = tid >> 5;
    if (lane == 0) warp_ss[wid] = ss;
    __syncthreads();
    if (tid == 0) {
        float tot = 0.f;
        #pragma unroll
        for (int i = 0; i < 8; i++) tot += warp_ss[i];
        s_scale = rsqrtf(tot / (float)HID + EPS);
    }
    __syncthreads();
    float scale = s_scale;

    float4 w0 = wr[tid];
    float4 w1 = wr[tid + 256];
    float4 o0, o1;
    o0.x = rna_tf32(v0.x * scale * w0.x); o0.y = rna_tf32(v0.y * scale * w0.y);
    o0.z = rna_tf32(v0.z * scale * w0.z); o0.w = rna_tf32(v0.w * scale * w0.w);
    o1.x = rna_tf32(v1.x * scale * w1.x); o1.y = rna_tf32(v1.y * scale * w1.y);
    o1.z = rna_tf32(v1.z * scale * w1.z); o1.w = rna_tf32(v1.w * scale * w1.w);
    orow[tid]       = o0;
    orow[tid + 256] = o1;
}

// ---------------- fp32 -> tf32(RNE) elementwise ----------------
__global__ __launch_bounds__(256) void to_tf32_kernel(
    const float4* __restrict__ s, float4* __restrict__ d, long n4)
{
    long i = (long)blockIdx.x * blockDim.x + threadIdx.x;
    long stride = (long)gridDim.x * blockDim.x;
    for (; i < n4; i += stride) {
        float4 v = s[i];
        v.x = rna_tf32(v.x); v.y = rna_tf32(v.y);
        v.z = rna_tf32(v.z); v.w = rna_tf32(v.w);
        d[i] = v;
    }
}

// ---------------- plain GEMM: C[M,N] = A @ W^T (+R) via mma.sync tf32 ----------------
// CTA tile 128x128, BK=32, 4-stage cp.async, 8 warps (2 M x 4 N), warp tile 64x32.
// EPI 0: C = rna(A@W^T);  EPI 1: C = R + A@W^T
template<int EPI>
__global__ __launch_bounds__(256, 1) void gemm_mma(
    const float* __restrict__ A, const float* __restrict__ W,
    const float* __restrict__ R, float* __restrict__ C, int K, int N)
{
    extern __shared__ __align__(1024) char smem[];
    uint32_t sb = s2u(smem);
    int tid = threadIdx.x;
    int lane = tid & 31, w = tid >> 5;
    int wm = w >> 2;      // 0..1
    int wn = w & 3;       // 0..3
    size_t row0 = (size_t)blockIdx.x * 128;
    size_t col0 = (size_t)blockIdx.y * 128;
    const int NK = K / BK;

    const float* Abase = A + row0 * (size_t)K;
    const float* Wbase = W + col0 * (size_t)K;

    auto load_stage = [&](int slot, int j) {
        uint32_t ab = sb + (uint32_t)slot * STAGE_B;
        uint32_t bb = ab + A_TILE_B;
        int kt = j * BK;
        #pragma unroll
        for (int p = 0; p < 4; p++) {
            int idx = p * 256 + tid;
            int r = idx >> 3, c = idx & 7;
            cpa16(ab + sw128((r << 7) + (c << 4)),
                  (const char*)(Abase + (size_t)r * K + kt) + (c << 4));
        }
        #pragma unroll
        for (int p = 0; p < 4; p++) {
            int idx = p * 256 + tid;
            int r = idx >> 3, c = idx & 7;
            cpa16(bb + sw128((r << 7) + (c << 4)),
                  (const char*)(Wbase + (size_t)r * K + kt) + (c << 4));
        }
    };

    float acc[4][4][4];
    #pragma unroll
    for (int i = 0; i < 4; i++)
        #pragma unroll
        for (int jx = 0; jx < 4; jx++)
            #pragma unroll
            for (int e = 0; e < 4; e++) acc[i][jx][e] = 0.f;

    #pragma unroll
    for (int p = 0; p < STAGES; p++) {
        if (p < NK) load_stage(p, p);
        asm volatile("cp.async.commit_group;");
    }

    for (int j = 0; j < NK; j++) {
        asm volatile("cp.async.wait_group %0;" :: "n"(STAGES - 1));
        __syncthreads();
        int slot = j & 3;
        uint32_t ab = sb + (uint32_t)slot * STAGE_B;
        uint32_t bb = ab + A_TILE_B;

        #pragma unroll
        for (int kk = 0; kk < 4; kk++) {
            uint32_t afr[4][4];
            #pragma unroll
            for (int mi = 0; mi < 4; mi++) {
                uint32_t off = (uint32_t)((wm * 64 + mi * 16 + (lane & 15)) << 7)
                             + (uint32_t)((kk << 5) + ((lane >> 4) << 4));
                ldsm4(afr[mi][0], afr[mi][1], afr[mi][2], afr[mi][3], ab + sw128(off));
            }
            uint32_t bfr[4][2];
            #pragma unroll
            for (int bi = 0; bi < 2; bi++) {
                uint32_t off = (uint32_t)((wn * 32 + bi * 16 + ((lane >> 4) << 3) + (lane & 7)) << 7)
                             + (uint32_t)((kk << 5) + (((lane >> 3) & 1) << 4));
                ldsm4(bfr[2*bi][0], bfr[2*bi][1], bfr[2*bi+1][0], bfr[2*bi+1][1],
                      bb + sw128(off));
            }
            #pragma unroll
            for (int mi = 0; mi < 4; mi++)
                #pragma unroll
                for (int nj = 0; nj < 4; nj++)
                    mma_tf32(acc[mi][nj], afr[mi], bfr[nj][0], bfr[nj][1]);
        }
        __syncthreads();
        if (j + STAGES < NK) load_stage(slot, j + STAGES);
        asm volatile("cp.async.commit_group;");
    }

    // epilogue
    #pragma unroll
    for (int mi = 0; mi < 4; mi++) {
        size_t r = row0 + wm * 64 + mi * 16 + (lane >> 2);
        #pragma unroll
        for (int nj = 0; nj < 4; nj++) {
            size_t c = col0 + wn * 32 + nj * 8 + 2 * (lane & 3);
            float* d0 = C + r * (size_t)N + c;
            float* d1 = C + (r + 8) * (size_t)N + c;
            float2 v0 = make_float2(acc[mi][nj][0], acc[mi][nj][1]);
            float2 v1 = make_float2(acc[mi][nj][2], acc[mi][nj][3]);
            if (EPI == 1) {
                const float2 r0 = *(const float2*)(R + r * (size_t)N + c);
                const float2 r1 = *(const float2*)(R + (r + 8) * (size_t)N + c);
                v0.x += r0.x; v0.y += r0.y;
                v1.x += r1.x; v1.y += r1.y;
            } else {
                v0.x = rna_tf32(v0.x); v0.y = rna_tf32(v0.y);
                v1.x = rna_tf32(v1.x); v1.y = rna_tf32(v1.y);
            }
            *(float2*)d0 = v0;
            *(float2*)d1 = v1;
        }
    }
}

// ---------------- fused gate/up GEMM: act = rna(silu(A@Wg^T) * (A@Wu^T)) ----------------
// CTA tile 128(M) x 64(N-inter), both Wg and Wu tiles per stage.
// 8 warps (4 M x 2 N), warp tile 32x32 of BOTH gate and up.
__global__ __launch_bounds__(256, 1) void gemm_gateup_mma(
    const float* __restrict__ A, const float* __restrict__ Wg,
    const float* __restrict__ Wu, float* __restrict__ C, int K, int N)
{
    extern __shared__ __align__(1024) char smem[];
    uint32_t sb = s2u(smem);
    int tid = threadIdx.x;
    int lane = tid & 31, w = tid >> 5;
    int wm = w & 3;       // 0..3 (M in 32-row slices)
    int wn = w >> 2;      // 0..1 (N in 32-col slices)
    size_t row0 = (size_t)blockIdx.x * 128;
    size_t col0 = (size_t)blockIdx.y * 64;
    const int NK = K / BK;

    const float* Abase = A + row0 * (size_t)K;
    const float* Gbase = Wg + col0 * (size_t)K;
    const float* Ubase = Wu + col0 * (size_t)K;

    auto load_stage = [&](int slot, int j) {
        uint32_t ab = sb + (uint32_t)slot * STAGE_B;
        uint32_t gb = ab + A_TILE_B;
        uint32_t ub = gb + 8192;
        int kt = j * BK;
        #pragma unroll
        for (int p = 0; p < 4; p++) {
            int idx = p * 256 + tid;
            int r = idx >> 3, c = idx & 7;
            cpa16(ab + sw128((r << 7) + (c << 4)),
                  (const char*)(Abase + (size_t)r * K + kt) + (c << 4));
        }
        #pragma unroll
        for (int p = 0; p < 2; p++) {
            int idx = p * 256 + tid;
            int r = idx >> 3, c = idx & 7;
            cpa16(gb + sw128((r << 7) + (c << 4)),
                  (const char*)(Gbase + (size_t)r * K + kt) + (c << 4));
        }
        #pragma unroll
        for (int p = 0; p < 2; p++) {
            int idx = p * 256 + tid;
            int r = idx >> 3, c = idx & 7;
            cpa16(ub + sw128((r << 7) + (c << 4)),
                  (const char*)(Ubase + (size_t)r * K + kt) + (c << 4));
        }
    };

    float accg[2][4][4], accu[2][4][4];
    #pragma unroll
    for (int i = 0; i < 2; i++)
        #pragma unroll
        for (int jx = 0; jx < 4; jx++)
            #pragma unroll
            for (int e = 0; e < 4; e++) { accg[i][jx][e] = 0.f; accu[i][jx][e] = 0.f; }

    #pragma unroll
    for (int p = 0; p < STAGES; p++) {
        if (p < NK) load_stage(p, p);
        asm volatile("cp.async.commit_group;");
    }

    for (int j = 0; j < NK; j++) {
        asm volatile("cp.async.wait_group %0;" :: "n"(STAGES - 1));
        __syncthreads();
        int slot = j & 3;
        uint32_t ab = sb + (uint32_t)slot * STAGE_B;
        uint32_t gb = ab + A_TILE_B;
        uint32_t ub = gb + 8192;

        #pragma unroll
        for (int kk = 0; kk < 4; kk++) {
            uint32_t afr[2][4];
            #pragma unroll
            for (int mi = 0; mi < 2; mi++) {
                uint32_t off = (uint32_t)((wm * 32 + mi * 16 + (lane & 15)) << 7)
                             + (uint32_t)((kk << 5) + ((lane >> 4) << 4));
                ldsm4(afr[mi][0], afr[mi][1], afr[mi][2], afr[mi][3], ab + sw128(off));
            }
            uint32_t gfr[4][2], ufr[4][2];
            #pragma unroll
            for (int bi = 0; bi < 2; bi++) {
                uint32_t off = (uint32_t)((wn * 32 + bi * 16 + ((lane >> 4) << 3) + (lane & 7)) << 7)
                             + (uint32_t)((kk << 5) + (((lane >> 3) & 1) << 4));
                uint32_t swo = sw128(off);
                ldsm4(gfr[2*bi][0], gfr[2*bi][1], gfr[2*bi+1][0], gfr[2*bi+1][1], gb + swo);
                ldsm4(ufr[2*bi][0], ufr[2*bi][1], ufr[2*bi+1][0], ufr[2*bi+1][1], ub + swo);
            }
            #pragma unroll
            for (int mi = 0; mi < 2; mi++)
                #pragma unroll
                for (int nj = 0; nj < 4; nj++) {
                    mma_tf32(accg[mi][nj], afr[mi], gfr[nj][0], gfr[nj][1]);
                    mma_tf32(accu[mi][nj], afr[mi], ufr[nj][0], ufr[nj][1]);
                }
        }
        __syncthreads();
        if (j + STAGES < NK) load_stage(slot, j + STAGES);
        asm volatile("cp.async.commit_group;");
    }

    // epilogue: silu(gate) * up, tf32-rounded
    #pragma unroll
    for (int mi = 0; mi < 2; mi++) {
        size_t r = row0 + wm * 32 + mi * 16 + (lane >> 2);
        #pragma unroll
        for (int nj = 0; nj < 4; nj++) {
            size_t c = col0 + wn * 32 + nj * 8 + 2 * (lane & 3);
            float2 v0, v1;
            {
                float gx = accg[mi][nj][0], ux = accu[mi][nj][0];
                v0.x = rna_tf32(gx / (1.f + expf(-gx)) * ux);
                float gy = accg[mi][nj][1], uy = accu[mi][nj][1];
                v0.y = rna_tf32(gy / (1.f + expf(-gy)) * uy);
                float gz = accg[mi][nj][2], uz = accu[mi][nj][2];
                v1.x = rna_tf32(gz / (1.f + expf(-gz)) * uz);
                float gw = accg[mi][nj][3], uw = accu[mi][nj][3];
                v1.y = rna_tf32(gw / (1.f + expf(-gw)) * uw);
            }
            *(float2*)(C + r * (size_t)N + c) = v0;
            *(float2*)(C + (r + 8) * (size_t)N + c) = v1;
        }
    }
}

// ---------------- launch ----------------
extern "C" void kernel_launch(void* const* d_in, const int* in_sizes, int n_in,
                              void* d_out, int out_size)
{
    const float* x      = (const float*)d_in[0];
    const float* in_w   = (const float*)d_in[2];
    const float* post_w = (const float*)d_in[3];
    const float* Wq     = (const float*)d_in[4];
    const float* Wo     = (const float*)d_in[5];
    const float* Wg     = (const float*)d_in[6];
    const float* Wu     = (const float*)d_in[7];
    const float* Wd     = (const float*)d_in[8];
    float* out = (float*)d_out;

    float *hnorm, *q, *hidden, *hpost, *act;
    float *tWq, *tWo, *tWg, *tWu, *tWd;
    cudaGetSymbolAddress((void**)&hnorm,  g_hnorm);
    cudaGetSymbolAddress((void**)&q,      g_q);
    cudaGetSymbolAddress((void**)&hidden, g_hidden);
    cudaGetSymbolAddress((void**)&hpost,  g_hpost);
    cudaGetSymbolAddress((void**)&act,    g_act);
    cudaGetSymbolAddress((void**)&tWq,    g_tWq);
    cudaGetSymbolAddress((void**)&tWo,    g_tWo);
    cudaGetSymbolAddress((void**)&tWg,    g_tWg);
    cudaGetSymbolAddress((void**)&tWu,    g_tWu);
    cudaGetSymbolAddress((void**)&tWd,    g_tWd);

    static bool attr_done = false;
    if (!attr_done) {
        cudaFuncSetAttribute(gemm_mma<0>, cudaFuncAttributeMaxDynamicSharedMemorySize, SMEM_TOTAL);
        cudaFuncSetAttribute(gemm_mma<1>, cudaFuncAttributeMaxDynamicSharedMemorySize, SMEM_TOTAL);
        cudaFuncSetAttribute(gemm_gateup_mma, cudaFuncAttributeMaxDynamicSharedMemorySize, SMEM_TOTAL);
        attr_done = true;
    }

    // weights -> tf32 (RNE) scratch copies
    const int CB = 1184;
    to_tf32_kernel<<<CB, 256>>>((const float4*)Wq, (float4*)tWq, (long)HID * HID / 4);
    to_tf32_kernel<<<CB, 256>>>((const float4*)Wo, (float4*)tWo, (long)HID * HID / 4);
    to_tf32_kernel<<<CB, 256>>>((const float4*)Wg, (float4*)tWg, (long)INTERD * HID / 4);
    to_tf32_kernel<<<CB, 256>>>((const float4*)Wu, (float4*)tWu, (long)INTERD * HID / 4);
    to_tf32_kernel<<<CB, 256>>>((const float4*)Wd, (float4*)tWd, (long)HID * INTERD / 4);

    // 1. h_norm = rna(rmsnorm(x) * in_w)
    rmsnorm_kernel<<<T_TOK, 256>>>(x, in_w, hnorm);
    // 2. q = rna(h_norm @ Wq^T)
    gemm_mma<0><<<dim3(T_TOK/128, HID/128), 256, SMEM_TOTAL>>>(hnorm, tWq, nullptr, q, HID, HID);
    // 3. hidden = x + q @ Wo^T
    gemm_mma<1><<<dim3(T_TOK/128, HID/128), 256, SMEM_TOTAL>>>(q, tWo, x, hidden, HID, HID);
    // 4. h_post = rna(rmsnorm(hidden) * post_w)
    rmsnorm_kernel<<<T_TOK, 256>>>(hidden, post_w, hpost);
    // 5. act = rna(silu(h_post @ Wg^T) * (h_post @ Wu^T))   [10944 = 171 * 64 exact]
    gemm_gateup_mma<<<dim3(T_TOK/128, INTERD/64), 256, SMEM_TOTAL>>>(hpost, tWg, tWu, act, HID, INTERD);
    // 6. out = hidden + act @ Wd^T
    gemm_mma<1><<<dim3(T_TOK/128, HID/128), 256, SMEM_TOTAL>>>(act, tWd, hidden, out, INTERD, HID);
}

// round 5
// speedup vs baseline: 4.2196x; 1.1401x over previous
#include <cuda_runtime.h>
#include <cstdint>
#include <math.h>

#define T_TOK  4096
#define HID    2048
#define INTERD 10944
#define EPS    1e-6f

#define BK 32
#define STAGES 4
// plain: A 128x32 tf32 (16KB) + B 256x32 (32KB); gateup: A 16KB + G 16KB + U 16KB
#define STAGE_B  49152
#define SMEM_TOTAL (STAGES * STAGE_B)  // 196608

// ---------------- scratch (device globals; allocation-free rule) ----------------
__device__ float g_hnorm [(size_t)T_TOK * HID];
__device__ float g_q     [(size_t)T_TOK * HID];
__device__ float g_hidden[(size_t)T_TOK * HID];
__device__ float g_hpost [(size_t)T_TOK * HID];
__device__ float g_act   [(size_t)T_TOK * INTERD];
__device__ float g_tWq   [(size_t)HID * HID];
__device__ float g_tWo   [(size_t)HID * HID];
__device__ float g_tWg   [(size_t)INTERD * HID];
__device__ float g_tWu   [(size_t)INTERD * HID];
__device__ float g_tWd   [(size_t)HID * INTERD];

// ---------------- PTX helpers ----------------
static __device__ __forceinline__ uint32_t s2u(const void* p) {
    uint32_t a;
    asm("{ .reg .u64 t; cvta.to.shared.u64 t, %1; cvt.u32.u64 %0, t; }" : "=r"(a) : "l"(p));
    return a;
}
static __device__ __forceinline__ float rna_tf32(float x) {
    uint32_t u;
    asm("cvt.rna.tf32.f32 %0, %1;" : "=r"(u) : "f"(x));
    return __uint_as_float(u);
}
static __device__ __forceinline__ void cpa16(uint32_t s, const void* g) {
    asm volatile("cp.async.cg.shared.global [%0], [%1], 16;" :: "r"(s), "l"(g));
}
static __device__ __forceinline__ void ldsm4(uint32_t& r0, uint32_t& r1,
                                             uint32_t& r2, uint32_t& r3, uint32_t addr) {
    asm volatile("ldmatrix.sync.aligned.m8n8.x4.shared.b16 {%0,%1,%2,%3}, [%4];"
                 : "=r"(r0), "=r"(r1), "=r"(r2), "=r"(r3) : "r"(addr));
}
static __device__ __forceinline__ void mma_tf32(float* c, const uint32_t* a,
                                                uint32_t b0, uint32_t b1) {
    asm volatile(
        "mma.sync.aligned.m16n8k8.row.col.f32.tf32.tf32.f32 "
        "{%0,%1,%2,%3}, {%4,%5,%6,%7}, {%8,%9}, {%0,%1,%2,%3};"
        : "+f"(c[0]), "+f"(c[1]), "+f"(c[2]), "+f"(c[3])
        : "r"(a[0]), "r"(a[1]), "r"(a[2]), "r"(a[3]), "r"(b0), "r"(b1));
}
static __device__ __forceinline__ uint32_t sw128(uint32_t off) {
    return off ^ ((off >> 3) & 0x70);
}

// ---------------- RMSNorm (fp32 in, tf32-RNE out) ----------------
__global__ __launch_bounds__(256) void rmsnorm_kernel(
    const float* __restrict__ x, const float* __restrict__ w, float* __restrict__ out)
{
    long row = blockIdx.x;
    const float4* xr = (const float4*)(x + row * (long)HID);
    const float4* wr = (const float4*)w;
    float4* orow = (float4*)(out + row * (long)HID);
    int tid = threadIdx.x;

    float4 v0 = xr[tid];
    float4 v1 = xr[tid + 256];
    float ss = v0.x*v0.x + v0.y*v0.y + v0.z*v0.z + v0.w*v0.w
             + v1.x*v1.x + v1.y*v1.y + v1.z*v1.z + v1.w*v1.w;

    #pragma unroll
    for (int off = 16; off > 0; off >>= 1)
        ss += __shfl_xor_sync(0xffffffffu, ss, off);

    __shared__ float warp_ss[8];
    __shared__ float s_scale;
    int lane = tid & 31, wid = tid >> 5;
    if (lane == 0) warp_ss[wid] = ss;
    __syncthreads();
    if (tid == 0) {
        float tot = 0.f;
        #pragma unroll
        for (int i = 0; i < 8; i++) tot += warp_ss[i];
        s_scale = rsqrtf(tot / (float)HID + EPS);
    }
    __syncthreads();
    float scale = s_scale;

    float4 w0 = wr[tid];
    float4 w1 = wr[tid + 256];
    float4 o0, o1;
    o0.x = rna_tf32(v0.x * scale * w0.x); o0.y = rna_tf32(v0.y * scale * w0.y);
    o0.z = rna_tf32(v0.z * scale * w0.z); o0.w = rna_tf32(v0.w * scale * w0.w);
    o1.x = rna_tf32(v1.x * scale * w1.x); o1.y = rna_tf32(v1.y * scale * w1.y);
    o1.z = rna_tf32(v1.z * scale * w1.z); o1.w = rna_tf32(v1.w * scale * w1.w);
    orow[tid]       = o0;
    orow[tid + 256] = o1;
}

// ---------------- fp32 -> tf32(RNE) elementwise ----------------
__global__ __launch_bounds__(256) void to_tf32_kernel(
    const float4* __restrict__ s, float4* __restrict__ d, long n4)
{
    long i = (long)blockIdx.x * blockDim.x + threadIdx.x;
    long stride = (long)gridDim.x * blockDim.x;
    for (; i < n4; i += stride) {
        float4 v = s[i];
        v.x = rna_tf32(v.x); v.y = rna_tf32(v.y);
        v.z = rna_tf32(v.z); v.w = rna_tf32(v.w);
        d[i] = v;
    }
}

// ---------------- plain GEMM: C[M,N] = A @ W^T (+R), mma.sync tf32 ----------------
// CTA tile 128x256, BK=32, 4-stage cp.async, 8 warps (2M x 4N), warp tile 64x64.
// EPI 0: C = rna(A@W^T);  EPI 1: C = R + A@W^T
template<int EPI>
__global__ __launch_bounds__(256, 1) void gemm_mma(
    const float* __restrict__ A, const float* __restrict__ W,
    const float* __restrict__ R, float* __restrict__ C, int K, int N)
{
    extern __shared__ __align__(1024) char smem[];
    uint32_t sb = s2u(smem);
    int tid = threadIdx.x;
    int lane = tid & 31, w = tid >> 5;
    int wm = w >> 2;      // 0..1  (64-row slice)
    int wn = w & 3;       // 0..3  (64-col slice)
    size_t row0 = (size_t)blockIdx.x * 128;
    size_t col0 = (size_t)blockIdx.y * 256;
    const int NK = K / BK;

    const float* Abase = A + row0 * (size_t)K;
    const float* Wbase = W + col0 * (size_t)K;

    auto load_stage = [&](int slot, int j) {
        uint32_t ab = sb + (uint32_t)slot * STAGE_B;
        uint32_t bb = ab + 16384;
        int kt = j * BK;
        #pragma unroll
        for (int p = 0; p < 4; p++) {
            int idx = p * 256 + tid;
            int r = idx >> 3, c = idx & 7;
            cpa16(ab + sw128((r << 7) + (c << 4)),
                  (const char*)(Abase + (size_t)r * K + kt) + (c << 4));
        }
        #pragma unroll
        for (int p = 0; p < 8; p++) {
            int idx = p * 256 + tid;
            int r = idx >> 3, c = idx & 7;
            cpa16(bb + sw128((r << 7) + (c << 4)),
                  (const char*)(Wbase + (size_t)r * K + kt) + (c << 4));
        }
    };

    float acc[4][8][4];
    #pragma unroll
    for (int i = 0; i < 4; i++)
        #pragma unroll
        for (int jx = 0; jx < 8; jx++)
            #pragma unroll
            for (int e = 0; e < 4; e++) acc[i][jx][e] = 0.f;

    #pragma unroll
    for (int p = 0; p < STAGES; p++) {
        if (p < NK) load_stage(p, p);
        asm volatile("cp.async.commit_group;");
    }

    for (int j = 0; j < NK; j++) {
        asm volatile("cp.async.wait_group %0;" :: "n"(STAGES - 1));
        __syncthreads();
        int slot = j & 3;
        uint32_t ab = sb + (uint32_t)slot * STAGE_B;
        uint32_t bb = ab + 16384;

        #pragma unroll
        for (int kk = 0; kk < 4; kk++) {
            uint32_t afr[4][4];
            #pragma unroll
            for (int mi = 0; mi < 4; mi++) {
                uint32_t off = (uint32_t)((wm * 64 + mi * 16 + (lane & 15)) << 7)
                             + (uint32_t)((kk << 5) + ((lane >> 4) << 4));
                ldsm4(afr[mi][0], afr[mi][1], afr[mi][2], afr[mi][3], ab + sw128(off));
            }
            uint32_t bfr[8][2];
            #pragma unroll
            for (int bi = 0; bi < 4; bi++) {
                uint32_t off = (uint32_t)((wn * 64 + bi * 16 + ((lane >> 4) << 3) + (lane & 7)) << 7)
                             + (uint32_t)((kk << 5) + (((lane >> 3) & 1) << 4));
                ldsm4(bfr[2*bi][0], bfr[2*bi][1], bfr[2*bi+1][0], bfr[2*bi+1][1],
                      bb + sw128(off));
            }
            #pragma unroll
            for (int mi = 0; mi < 4; mi++)
                #pragma unroll
                for (int nj = 0; nj < 8; nj++)
                    mma_tf32(acc[mi][nj], afr[mi], bfr[nj][0], bfr[nj][1]);
        }
        __syncthreads();
        if (j + STAGES < NK) load_stage(slot, j + STAGES);
        asm volatile("cp.async.commit_group;");
    }

    // epilogue
    #pragma unroll
    for (int mi = 0; mi < 4; mi++) {
        size_t r = row0 + wm * 64 + mi * 16 + (lane >> 2);
        #pragma unroll
        for (int nj = 0; nj < 8; nj++) {
            size_t c = col0 + wn * 64 + nj * 8 + 2 * (lane & 3);
            float* d0 = C + r * (size_t)N + c;
            float* d1 = C + (r + 8) * (size_t)N + c;
            float2 v0 = make_float2(acc[mi][nj][0], acc[mi][nj][1]);
            float2 v1 = make_float2(acc[mi][nj][2], acc[mi][nj][3]);
            if (EPI == 1) {
                const float2 r0 = *(const float2*)(R + r * (size_t)N + c);
                const float2 r1 = *(const float2*)(R + (r + 8) * (size_t)N + c);
                v0.x += r0.x; v0.y += r0.y;
                v1.x += r1.x; v1.y += r1.y;
            } else {
                v0.x = rna_tf32(v0.x); v0.y = rna_tf32(v0.y);
                v1.x = rna_tf32(v1.x); v1.y = rna_tf32(v1.y);
            }
            *(float2*)d0 = v0;
            *(float2*)d1 = v1;
        }
    }
}

// ---------------- fused gate/up GEMM: act = rna(silu(A@Wg^T) * (A@Wu^T)) ----------------
// CTA tile 128(M) x 128(inter), 8 warps (4M x 2N), warp tile 32 x 64 of BOTH g and u.
// Last inter-tile is ragged (10944 = 85*128 + 64): predicated loads + stores.
__global__ __launch_bounds__(256, 1) void gemm_gateup_mma(
    const float* __restrict__ A, const float* __restrict__ Wg,
    const float* __restrict__ Wu, float* __restrict__ C, int K, int N)
{
    extern __shared__ __align__(1024) char smem[];
    uint32_t sb = s2u(smem);
    int tid = threadIdx.x;
    int lane = tid & 31, w = tid >> 5;
    int wm = w & 3;       // 0..3 (32-row slice)
    int wn = w >> 2;      // 0..1 (64-col slice)
    size_t row0 = (size_t)blockIdx.x * 128;
    size_t col0 = (size_t)blockIdx.y * 128;
    const int NK = K / BK;

    const float* Abase = A + row0 * (size_t)K;
    const float* Gbase = Wg + col0 * (size_t)K;
    const float* Ubase = Wu + col0 * (size_t)K;
    int nvalid = (int)((size_t)N - col0 < 128 ? (size_t)N - col0 : 128);

    auto load_stage = [&](int slot, int j) {
        uint32_t ab = sb + (uint32_t)slot * STAGE_B;
        uint32_t gb = ab + 16384;
        uint32_t ub = gb + 16384;
        int kt = j * BK;
        #pragma unroll
        for (int p = 0; p < 4; p++) {
            int idx = p * 256 + tid;
            int r = idx >> 3, c = idx & 7;
            cpa16(ab + sw128((r << 7) + (c << 4)),
                  (const char*)(Abase + (size_t)r * K + kt) + (c << 4));
        }
        #pragma unroll
        for (int p = 0; p < 4; p++) {
            int idx = p * 256 + tid;
            int r = idx >> 3, c = idx & 7;
            if (r < nvalid) {
                uint32_t swo = sw128((r << 7) + (c << 4));
                cpa16(gb + swo, (const char*)(Gbase + (size_t)r * K + kt) + (c << 4));
                cpa16(ub + swo, (const char*)(Ubase + (size_t)r * K + kt) + (c << 4));
            }
        }
    };

    float accg[2][8][4], accu[2][8][4];
    #pragma unroll
    for (int i = 0; i < 2; i++)
        #pragma unroll
        for (int jx = 0; jx < 8; jx++)
            #pragma unroll
            for (int e = 0; e < 4; e++) { accg[i][jx][e] = 0.f; accu[i][jx][e] = 0.f; }

    #pragma unroll
    for (int p = 0; p < STAGES; p++) {
        if (p < NK) load_stage(p, p);
        asm volatile("cp.async.commit_group;");
    }

    for (int j = 0; j < NK; j++) {
        asm volatile("cp.async.wait_group %0;" :: "n"(STAGES - 1));
        __syncthreads();
        int slot = j & 3;
        uint32_t ab = sb + (uint32_t)slot * STAGE_B;
        uint32_t gb = ab + 16384;
        uint32_t ub = gb + 16384;

        #pragma unroll
        for (int kk = 0; kk < 4; kk++) {
            uint32_t afr[2][4];
            #pragma unroll
            for (int mi = 0; mi < 2; mi++) {
                uint32_t off = (uint32_t)((wm * 32 + mi * 16 + (lane & 15)) << 7)
                             + (uint32_t)((kk << 5) + ((lane >> 4) << 4));
                ldsm4(afr[mi][0], afr[mi][1], afr[mi][2], afr[mi][3], ab + sw128(off));
            }
            uint32_t gfr[8][2], ufr[8][2];
            #pragma unroll
            for (int bi = 0; bi < 4; bi++) {
                uint32_t off = (uint32_t)((wn * 64 + bi * 16 + ((lane >> 4) << 3) + (lane & 7)) << 7)
                             + (uint32_t)((kk << 5) + (((lane >> 3) & 1) << 4));
                uint32_t swo = sw128(off);
                ldsm4(gfr[2*bi][0], gfr[2*bi][1], gfr[2*bi+1][0], gfr[2*bi+1][1], gb + swo);
                ldsm4(ufr[2*bi][0], ufr[2*bi][1], ufr[2*bi+1][0], ufr[2*bi+1][1], ub + swo);
            }
            #pragma unroll
            for (int mi = 0; mi < 2; mi++)
                #pragma unroll
                for (int nj = 0; nj < 8; nj++) {
                    mma_tf32(accg[mi][nj], afr[mi], gfr[nj][0], gfr[nj][1]);
                    mma_tf32(accu[mi][nj], afr[mi], ufr[nj][0], ufr[nj][1]);
                }
        }
        __syncthreads();
        if (j + STAGES < NK) load_stage(slot, j + STAGES);
        asm volatile("cp.async.commit_group;");
    }

    // epilogue: silu(gate) * up, tf32-rounded, predicated on N
    #pragma unroll
    for (int mi = 0; mi < 2; mi++) {
        size_t r = row0 + wm * 32 + mi * 16 + (lane >> 2);
        #pragma unroll
        for (int nj = 0; nj < 8; nj++) {
            size_t c = col0 + wn * 64 + nj * 8 + 2 * (lane & 3);
            if (c < (size_t)N) {
                float2 v0, v1;
                float gx = accg[mi][nj][0], ux = accu[mi][nj][0];
                v0.x = rna_tf32(gx / (1.f + expf(-gx)) * ux);
                float gy = accg[mi][nj][1], uy = accu[mi][nj][1];
                v0.y = rna_tf32(gy / (1.f + expf(-gy)) * uy);
                float gz = accg[mi][nj][2], uz = accu[mi][nj][2];
                v1.x = rna_tf32(gz / (1.f + expf(-gz)) * uz);
                float gw = accg[mi][nj][3], uw = accu[mi][nj][3];
                v1.y = rna_tf32(gw / (1.f + expf(-gw)) * uw);
                *(float2*)(C + r * (size_t)N + c) = v0;
                *(float2*)(C + (r + 8) * (size_t)N + c) = v1;
            }
        }
    }
}

// ---------------- launch ----------------
extern "C" void kernel_launch(void* const* d_in, const int* in_sizes, int n_in,
                              void* d_out, int out_size)
{
    const float* x      = (const float*)d_in[0];
    const float* in_w   = (const float*)d_in[2];
    const float* post_w = (const float*)d_in[3];
    const float* Wq     = (const float*)d_in[4];
    const float* Wo     = (const float*)d_in[5];
    const float* Wg     = (const float*)d_in[6];
    const float* Wu     = (const float*)d_in[7];
    const float* Wd     = (const float*)d_in[8];
    float* out = (float*)d_out;

    float *hnorm, *q, *hidden, *hpost, *act;
    float *tWq, *tWo, *tWg, *tWu, *tWd;
    cudaGetSymbolAddress((void**)&hnorm,  g_hnorm);
    cudaGetSymbolAddress((void**)&q,      g_q);
    cudaGetSymbolAddress((void**)&hidden, g_hidden);
    cudaGetSymbolAddress((void**)&hpost,  g_hpost);
    cudaGetSymbolAddress((void**)&act,    g_act);
    cudaGetSymbolAddress((void**)&tWq,    g_tWq);
    cudaGetSymbolAddress((void**)&tWo,    g_tWo);
    cudaGetSymbolAddress((void**)&tWg,    g_tWg);
    cudaGetSymbolAddress((void**)&tWu,    g_tWu);
    cudaGetSymbolAddress((void**)&tWd,    g_tWd);

    static bool attr_done = false;
    if (!attr_done) {
        cudaFuncSetAttribute(gemm_mma<0>, cudaFuncAttributeMaxDynamicSharedMemorySize, SMEM_TOTAL);
        cudaFuncSetAttribute(gemm_mma<1>, cudaFuncAttributeMaxDynamicSharedMemorySize, SMEM_TOTAL);
        cudaFuncSetAttribute(gemm_gateup_mma, cudaFuncAttributeMaxDynamicSharedMemorySize, SMEM_TOTAL);
        attr_done = true;
    }

    // weights -> tf32 (RNE) scratch copies
    const int CB = 1184;
    to_tf32_kernel<<<CB, 256>>>((const float4*)Wq, (float4*)tWq, (long)HID * HID / 4);
    to_tf32_kernel<<<CB, 256>>>((const float4*)Wo, (float4*)tWo, (long)HID * HID / 4);
    to_tf32_kernel<<<CB, 256>>>((const float4*)Wg, (float4*)tWg, (long)INTERD * HID / 4);
    to_tf32_kernel<<<CB, 256>>>((const float4*)Wu, (float4*)tWu, (long)INTERD * HID / 4);
    to_tf32_kernel<<<CB, 256>>>((const float4*)Wd, (float4*)tWd, (long)HID * INTERD / 4);

    // 1. h_norm = rna(rmsnorm(x) * in_w)
    rmsnorm_kernel<<<T_TOK, 256>>>(x, in_w, hnorm);
    // 2. q = rna(h_norm @ Wq^T)
    gemm_mma<0><<<dim3(T_TOK/128, HID/256), 256, SMEM_TOTAL>>>(hnorm, tWq, nullptr, q, HID, HID);
    // 3. hidden = x + q @ Wo^T
    gemm_mma<1><<<dim3(T_TOK/128, HID/256), 256, SMEM_TOTAL>>>(q, tWo, x, hidden, HID, HID);
    // 4. h_post = rna(rmsnorm(hidden) * post_w)
    rmsnorm_kernel<<<T_TOK, 256>>>(hidden, post_w, hpost);
    // 5. act = rna(silu(h_post @ Wg^T) * (h_post @ Wu^T))   [86 tiles, last ragged 64]
    gemm_gateup_mma<<<dim3(T_TOK/128, (INTERD + 127)/128), 256, SMEM_TOTAL>>>(hpost, tWg, tWu, act, HID, INTERD);
    // 6. out = hidden + act @ Wd^T
    gemm_mma<1><<<dim3(T_TOK/128, HID/256), 256, SMEM_TOTAL>>>(act, tWd, hidden, out, INTERD, HID);
}

// round 6
// speedup vs baseline: 7.9861x; 1.8926x over previous
#include <cuda_runtime.h>
#include <cuda_fp16.h>
#include <cstdint>
#include <math.h>

#define T_TOK  4096
#define HID    2048
#define INTERD 10944
#define EPS    1e-6f

#define BK 64            // 64 halves = 128 bytes per row
#define STAGES 4
// plain: A 128x64 fp16 (16KB) + B 256x64 (32KB); gateup: A 16KB + G 16KB + U 16KB
#define STAGE_B  49152
#define SMEM_TOTAL (STAGES * STAGE_B)  // 196608

// ---------------- scratch (device globals; allocation-free rule) ----------------
__device__ __half g_hnorm [(size_t)T_TOK * HID];
__device__ __half g_q     [(size_t)T_TOK * HID];
__device__ float  g_hidden[(size_t)T_TOK * HID];
__device__ __half g_hpost [(size_t)T_TOK * HID];
__device__ __half g_act   [(size_t)T_TOK * INTERD];
__device__ __half g_hWq   [(size_t)HID * HID];
__device__ __half g_hWo   [(size_t)HID * HID];
__device__ __half g_hWg   [(size_t)INTERD * HID];
__device__ __half g_hWu   [(size_t)INTERD * HID];
__device__ __half g_hWd   [(size_t)HID * INTERD];

// ---------------- PTX helpers ----------------
static __device__ __forceinline__ uint32_t s2u(const void* p) {
    uint32_t a;
    asm("{ .reg .u64 t; cvta.to.shared.u64 t, %1; cvt.u32.u64 %0, t; }" : "=r"(a) : "l"(p));
    return a;
}
static __device__ __forceinline__ void cpa16(uint32_t s, const void* g) {
    asm volatile("cp.async.cg.shared.global [%0], [%1], 16;" :: "r"(s), "l"(g));
}
static __device__ __forceinline__ void ldsm4(uint32_t& r0, uint32_t& r1,
                                             uint32_t& r2, uint32_t& r3, uint32_t addr) {
    asm volatile("ldmatrix.sync.aligned.m8n8.x4.shared.b16 {%0,%1,%2,%3}, [%4];"
                 : "=r"(r0), "=r"(r1), "=r"(r2), "=r"(r3) : "r"(addr));
}
static __device__ __forceinline__ void mma_f16(float* c, const uint32_t* a,
                                               uint32_t b0, uint32_t b1) {
    asm volatile(
        "mma.sync.aligned.m16n8k16.row.col.f32.f16.f16.f32 "
        "{%0,%1,%2,%3}, {%4,%5,%6,%7}, {%8,%9}, {%0,%1,%2,%3};"
        : "+f"(c[0]), "+f"(c[1]), "+f"(c[2]), "+f"(c[3])
        : "r"(a[0]), "r"(a[1]), "r"(a[2]), "r"(a[3]), "r"(b0), "r"(b1));
}
static __device__ __forceinline__ uint32_t sw128(uint32_t off) {
    return off ^ ((off >> 3) & 0x70);
}

// ---------------- RMSNorm (fp32 in, fp16-RNE out) ----------------
__global__ __launch_bounds__(256) void rmsnorm_kernel(
    const float* __restrict__ x, const float* __restrict__ w, __half* __restrict__ out)
{
    long row = blockIdx.x;
    const float4* xr = (const float4*)(x + row * (long)HID);
    const float4* wr = (const float4*)w;
    __half2* orow = (__half2*)(out + row * (long)HID);
    int tid = threadIdx.x;

    float4 v0 = xr[tid];
    float4 v1 = xr[tid + 256];
    float ss = v0.x*v0.x + v0.y*v0.y + v0.z*v0.z + v0.w*v0.w
             + v1.x*v1.x + v1.y*v1.y + v1.z*v1.z + v1.w*v1.w;

    #pragma unroll
    for (int off = 16; off > 0; off >>= 1)
        ss += __shfl_xor_sync(0xffffffffu, ss, off);

    __shared__ float warp_ss[8];
    __shared__ float s_scale;
    int lane = tid & 31, wid = tid >> 5;
    if (lane == 0) warp_ss[wid] = ss;
    __syncthreads();
    if (tid == 0) {
        float tot = 0.f;
        #pragma unroll
        for (int i = 0; i < 8; i++) tot += warp_ss[i];
        s_scale = rsqrtf(tot / (float)HID + EPS);
    }
    __syncthreads();
    float scale = s_scale;

    float4 w0 = wr[tid];
    float4 w1 = wr[tid + 256];
    orow[2*tid]       = __floats2half2_rn(v0.x * scale * w0.x, v0.y * scale * w0.y);
    orow[2*tid + 1]   = __floats2half2_rn(v0.z * scale * w0.z, v0.w * scale * w0.w);
    orow[2*tid + 512] = __floats2half2_rn(v1.x * scale * w1.x, v1.y * scale * w1.y);
    orow[2*tid + 513] = __floats2half2_rn(v1.z * scale * w1.z, v1.w * scale * w1.w);
}

// ---------------- fp32 -> fp16(RNE) elementwise ----------------
__global__ __launch_bounds__(256) void to_f16_kernel(
    const float4* __restrict__ s, uint2* __restrict__ d, long n4)
{
    long i = (long)blockIdx.x * blockDim.x + threadIdx.x;
    long stride = (long)gridDim.x * blockDim.x;
    for (; i < n4; i += stride) {
        float4 v = s[i];
        __half2 lo = __floats2half2_rn(v.x, v.y);
        __half2 hi = __floats2half2_rn(v.z, v.w);
        uint2 o;
        o.x = *(uint32_t*)&lo;
        o.y = *(uint32_t*)&hi;
        d[i] = o;
    }
}

// ---------------- plain GEMM: C[M,N] = A @ W^T (+R), mma.sync fp16 ----------------
// CTA tile 128x256, BK=64, 4-stage cp.async, 8 warps (2M x 4N), warp tile 64x64.
// EPI 0: C(half) = rn(A@W^T);  EPI 1: C(float) = R + A@W^T
template<int EPI>
__global__ __launch_bounds__(256, 1) void gemm_mma(
    const __half* __restrict__ A, const __half* __restrict__ W,
    const float* __restrict__ R, void* __restrict__ Cv, int K, int N)
{
    extern __shared__ __align__(1024) char smem[];
    uint32_t sb = s2u(smem);
    int tid = threadIdx.x;
    int lane = tid & 31, w = tid >> 5;
    int wm = w >> 2;      // 0..1  (64-row slice)
    int wn = w & 3;       // 0..3  (64-col slice)
    size_t row0 = (size_t)blockIdx.x * 128;
    size_t col0 = (size_t)blockIdx.y * 256;
    const int NK = K / BK;

    const __half* Abase = A + row0 * (size_t)K;
    const __half* Wbase = W + col0 * (size_t)K;

    auto load_stage = [&](int slot, int j) {
        uint32_t ab = sb + (uint32_t)slot * STAGE_B;
        uint32_t bb = ab + 16384;
        int kt = j * BK;
        #pragma unroll
        for (int p = 0; p < 4; p++) {
            int idx = p * 256 + tid;
            int r = idx >> 3, c = idx & 7;   // 8 x 16B chunks per 128B row
            cpa16(ab + sw128((r << 7) + (c << 4)),
                  (const char*)(Abase + (size_t)r * K + kt) + (c << 4));
        }
        #pragma unroll
        for (int p = 0; p < 8; p++) {
            int idx = p * 256 + tid;
            int r = idx >> 3, c = idx & 7;
            cpa16(bb + sw128((r << 7) + (c << 4)),
                  (const char*)(Wbase + (size_t)r * K + kt) + (c << 4));
        }
    };

    float acc[4][8][4];
    #pragma unroll
    for (int i = 0; i < 4; i++)
        #pragma unroll
        for (int jx = 0; jx < 8; jx++)
            #pragma unroll
            for (int e = 0; e < 4; e++) acc[i][jx][e] = 0.f;

    #pragma unroll
    for (int p = 0; p < STAGES; p++) {
        if (p < NK) load_stage(p, p);
        asm volatile("cp.async.commit_group;");
    }

    for (int j = 0; j < NK; j++) {
        asm volatile("cp.async.wait_group %0;" :: "n"(STAGES - 1));
        __syncthreads();
        int slot = j & 3;
        uint32_t ab = sb + (uint32_t)slot * STAGE_B;
        uint32_t bb = ab + 16384;

        #pragma unroll
        for (int kk = 0; kk < 4; kk++) {   // 4 x k16 = BK 64
            uint32_t afr[4][4];
            #pragma unroll
            for (int mi = 0; mi < 4; mi++) {
                // rows: wm*64 + mi*16 + (lane&15); halves col: kk*16 + (lane>>4)*8
                uint32_t off = (uint32_t)((wm * 64 + mi * 16 + (lane & 15)) << 7)
                             + (uint32_t)((kk << 5) + ((lane >> 4) << 4));
                ldsm4(afr[mi][0], afr[mi][1], afr[mi][2], afr[mi][3], ab + sw128(off));
            }
            uint32_t bfr[8][2];
            #pragma unroll
            for (int bi = 0; bi < 4; bi++) {
                uint32_t off = (uint32_t)((wn * 64 + bi * 16 + ((lane >> 4) << 3) + (lane & 7)) << 7)
                             + (uint32_t)((kk << 5) + (((lane >> 3) & 1) << 4));
                ldsm4(bfr[2*bi][0], bfr[2*bi][1], bfr[2*bi+1][0], bfr[2*bi+1][1],
                      bb + sw128(off));
            }
            #pragma unroll
            for (int mi = 0; mi < 4; mi++)
                #pragma unroll
                for (int nj = 0; nj < 8; nj++)
                    mma_f16(acc[mi][nj], afr[mi], bfr[nj][0], bfr[nj][1]);
        }
        __syncthreads();
        if (j + STAGES < NK) load_stage(slot, j + STAGES);
        asm volatile("cp.async.commit_group;");
    }

    // epilogue
    #pragma unroll
    for (int mi = 0; mi < 4; mi++) {
        size_t r = row0 + wm * 64 + mi * 16 + (lane >> 2);
        #pragma unroll
        for (int nj = 0; nj < 8; nj++) {
            size_t c = col0 + wn * 64 + nj * 8 + 2 * (lane & 3);
            if (EPI == 1) {
                float* C = (float*)Cv;
                const float2 r0 = *(const float2*)(R + r * (size_t)N + c);
                const float2 r1 = *(const float2*)(R + (r + 8) * (size_t)N + c);
                float2 v0 = make_float2(acc[mi][nj][0] + r0.x, acc[mi][nj][1] + r0.y);
                float2 v1 = make_float2(acc[mi][nj][2] + r1.x, acc[mi][nj][3] + r1.y);
                *(float2*)(C + r * (size_t)N + c) = v0;
                *(float2*)(C + (r + 8) * (size_t)N + c) = v1;
            } else {
                __half2* C = (__half2*)Cv;
                C[(r * (size_t)N + c) >> 1]       = __floats2half2_rn(acc[mi][nj][0], acc[mi][nj][1]);
                C[((r + 8) * (size_t)N + c) >> 1] = __floats2half2_rn(acc[mi][nj][2], acc[mi][nj][3]);
            }
        }
    }
}

// ---------------- fused gate/up GEMM: act(half) = rn(silu(A@Wg^T) * (A@Wu^T)) ----------------
// CTA tile 128(M) x 128(inter), 8 warps (4M x 2N), warp tile 32 x 64 of BOTH g and u.
// Last inter-tile ragged (10944 = 85*128 + 64): predicated loads + stores.
__global__ __launch_bounds__(256, 1) void gemm_gateup_mma(
    const __half* __restrict__ A, const __half* __restrict__ Wg,
    const __half* __restrict__ Wu, __half* __restrict__ C, int K, int N)
{
    extern __shared__ __align__(1024) char smem[];
    uint32_t sb = s2u(smem);
    int tid = threadIdx.x;
    int lane = tid & 31, w = tid >> 5;
    int wm = w & 3;       // 0..3 (32-row slice)
    int wn = w >> 2;      // 0..1 (64-col slice)
    size_t row0 = (size_t)blockIdx.x * 128;
    size_t col0 = (size_t)blockIdx.y * 128;
    const int NK = K / BK;

    const __half* Abase = A + row0 * (size_t)K;
    const __half* Gbase = Wg + col0 * (size_t)K;
    const __half* Ubase = Wu + col0 * (size_t)K;
    int nvalid = (int)((size_t)N - col0 < 128 ? (size_t)N - col0 : 128);

    auto load_stage = [&](int slot, int j) {
        uint32_t ab = sb + (uint32_t)slot * STAGE_B;
        uint32_t gb = ab + 16384;
        uint32_t ub = gb + 16384;
        int kt = j * BK;
        #pragma unroll
        for (int p = 0; p < 4; p++) {
            int idx = p * 256 + tid;
            int r = idx >> 3, c = idx & 7;
            cpa16(ab + sw128((r << 7) + (c << 4)),
                  (const char*)(Abase + (size_t)r * K + kt) + (c << 4));
        }
        #pragma unroll
        for (int p = 0; p < 4; p++) {
            int idx = p * 256 + tid;
            int r = idx >> 3, c = idx & 7;
            if (r < nvalid) {
                uint32_t swo = sw128((r << 7) + (c << 4));
                cpa16(gb + swo, (const char*)(Gbase + (size_t)r * K + kt) + (c << 4));
                cpa16(ub + swo, (const char*)(Ubase + (size_t)r * K + kt) + (c << 4));
            }
        }
    };

    float accg[2][8][4], accu[2][8][4];
    #pragma unroll
    for (int i = 0; i < 2; i++)
        #pragma unroll
        for (int jx = 0; jx < 8; jx++)
            #pragma unroll
            for (int e = 0; e < 4; e++) { accg[i][jx][e] = 0.f; accu[i][jx][e] = 0.f; }

    #pragma unroll
    for (int p = 0; p < STAGES; p++) {
        if (p < NK) load_stage(p, p);
        asm volatile("cp.async.commit_group;");
    }

    for (int j = 0; j < NK; j++) {
        asm volatile("cp.async.wait_group %0;" :: "n"(STAGES - 1));
        __syncthreads();
        int slot = j & 3;
        uint32_t ab = sb + (uint32_t)slot * STAGE_B;
        uint32_t gb = ab + 16384;
        uint32_t ub = gb + 16384;

        #pragma unroll
        for (int kk = 0; kk < 4; kk++) {
            uint32_t afr[2][4];
            #pragma unroll
            for (int mi = 0; mi < 2; mi++) {
                uint32_t off = (uint32_t)((wm * 32 + mi * 16 + (lane & 15)) << 7)
                             + (uint32_t)((kk << 5) + ((lane >> 4) << 4));
                ldsm4(afr[mi][0], afr[mi][1], afr[mi][2], afr[mi][3], ab + sw128(off));
            }
            uint32_t gfr[8][2], ufr[8][2];
            #pragma unroll
            for (int bi = 0; bi < 4; bi++) {
                uint32_t off = (uint32_t)((wn * 64 + bi * 16 + ((lane >> 4) << 3) + (lane & 7)) << 7)
                             + (uint32_t)((kk << 5) + (((lane >> 3) & 1) << 4));
                uint32_t swo = sw128(off);
                ldsm4(gfr[2*bi][0], gfr[2*bi][1], gfr[2*bi+1][0], gfr[2*bi+1][1], gb + swo);
                ldsm4(ufr[2*bi][0], ufr[2*bi][1], ufr[2*bi+1][0], ufr[2*bi+1][1], ub + swo);
            }
            #pragma unroll
            for (int mi = 0; mi < 2; mi++)
                #pragma unroll
                for (int nj = 0; nj < 8; nj++) {
                    mma_f16(accg[mi][nj], afr[mi], gfr[nj][0], gfr[nj][1]);
                    mma_f16(accu[mi][nj], afr[mi], ufr[nj][0], ufr[nj][1]);
                }
        }
        __syncthreads();
        if (j + STAGES < NK) load_stage(slot, j + STAGES);
        asm volatile("cp.async.commit_group;");
    }

    // epilogue: silu(gate) * up -> fp16, predicated on N
    #pragma unroll
    for (int mi = 0; mi < 2; mi++) {
        size_t r = row0 + wm * 32 + mi * 16 + (lane >> 2);
        #pragma unroll
        for (int nj = 0; nj < 8; nj++) {
            size_t c = col0 + wn * 64 + nj * 8 + 2 * (lane & 3);
            if (c < (size_t)N) {
                float gx = accg[mi][nj][0], ux = accu[mi][nj][0];
                float gy = accg[mi][nj][1], uy = accu[mi][nj][1];
                float gz = accg[mi][nj][2], uz = accu[mi][nj][2];
                float gw = accg[mi][nj][3], uw = accu[mi][nj][3];
                __half2 v0 = __floats2half2_rn(gx / (1.f + expf(-gx)) * ux,
                                               gy / (1.f + expf(-gy)) * uy);
                __half2 v1 = __floats2half2_rn(gz / (1.f + expf(-gz)) * uz,
                                               gw / (1.f + expf(-gw)) * uw);
                *(__half2*)(C + r * (size_t)N + c) = v0;
                *(__half2*)(C + (r + 8) * (size_t)N + c) = v1;
            }
        }
    }
}

// ---------------- launch ----------------
extern "C" void kernel_launch(void* const* d_in, const int* in_sizes, int n_in,
                              void* d_out, int out_size)
{
    const float* x      = (const float*)d_in[0];
    const float* in_w   = (const float*)d_in[2];
    const float* post_w = (const float*)d_in[3];
    const float* Wq     = (const float*)d_in[4];
    const float* Wo     = (const float*)d_in[5];
    const float* Wg     = (const float*)d_in[6];
    const float* Wu     = (const float*)d_in[7];
    const float* Wd     = (const float*)d_in[8];
    float* out = (float*)d_out;

    __half *hnorm, *q, *hpost, *act, *hWq, *hWo, *hWg, *hWu, *hWd;
    float *hidden;
    cudaGetSymbolAddress((void**)&hnorm,  g_hnorm);
    cudaGetSymbolAddress((void**)&q,      g_q);
    cudaGetSymbolAddress((void**)&hidden, g_hidden);
    cudaGetSymbolAddress((void**)&hpost,  g_hpost);
    cudaGetSymbolAddress((void**)&act,    g_act);
    cudaGetSymbolAddress((void**)&hWq,    g_hWq);
    cudaGetSymbolAddress((void**)&hWo,    g_hWo);
    cudaGetSymbolAddress((void**)&hWg,    g_hWg);
    cudaGetSymbolAddress((void**)&hWu,    g_hWu);
    cudaGetSymbolAddress((void**)&hWd,    g_hWd);

    static bool attr_done = false;
    if (!attr_done) {
        cudaFuncSetAttribute(gemm_mma<0>, cudaFuncAttributeMaxDynamicSharedMemorySize, SMEM_TOTAL);
        cudaFuncSetAttribute(gemm_mma<1>, cudaFuncAttributeMaxDynamicSharedMemorySize, SMEM_TOTAL);
        cudaFuncSetAttribute(gemm_gateup_mma, cudaFuncAttributeMaxDynamicSharedMemorySize, SMEM_TOTAL);
        attr_done = true;
    }

    // weights -> fp16 (RNE) scratch copies
    const int CB = 1184;
    to_f16_kernel<<<CB, 256>>>((const float4*)Wq, (uint2*)hWq, (long)HID * HID / 4);
    to_f16_kernel<<<CB, 256>>>((const float4*)Wo, (uint2*)hWo, (long)HID * HID / 4);
    to_f16_kernel<<<CB, 256>>>((const float4*)Wg, (uint2*)hWg, (long)INTERD * HID / 4);
    to_f16_kernel<<<CB, 256>>>((const float4*)Wu, (uint2*)hWu, (long)INTERD * HID / 4);
    to_f16_kernel<<<CB, 256>>>((const float4*)Wd, (uint2*)hWd, (long)HID * INTERD / 4);

    // 1. h_norm = rn(rmsnorm(x) * in_w)
    rmsnorm_kernel<<<T_TOK, 256>>>(x, in_w, hnorm);
    // 2. q = rn(h_norm @ Wq^T)
    gemm_mma<0><<<dim3(T_TOK/128, HID/256), 256, SMEM_TOTAL>>>(hnorm, hWq, nullptr, q, HID, HID);
    // 3. hidden = x + q @ Wo^T
    gemm_mma<1><<<dim3(T_TOK/128, HID/256), 256, SMEM_TOTAL>>>(q, hWo, x, hidden, HID, HID);
    // 4. h_post = rn(rmsnorm(hidden) * post_w)
    rmsnorm_kernel<<<T_TOK, 256>>>(hidden, post_w, hpost);
    // 5. act = rn(silu(h_post @ Wg^T) * (h_post @ Wu^T))   [86 tiles, last ragged 64]
    gemm_gateup_mma<<<dim3(T_TOK/128, (INTERD + 127)/128), 256, SMEM_TOTAL>>>(hpost, hWg, hWu, act, HID, INTERD);
    // 6. out = hidden + act @ Wd^T
    gemm_mma<1><<<dim3(T_TOK/128, HID/256), 256, SMEM_TOTAL>>>(act, hWd, hidden, out, INTERD, HID);
}

// round 7
// speedup vs baseline: 8.1531x; 1.0209x over previous
#include <cuda_runtime.h>
#include <cuda_fp16.h>
#include <cstdint>
#include <math.h>

#define T_TOK  4096
#define HID    2048
#define INTERD 10944
#define EPS    1e-6f

#define BK 64            // 64 halves = 128 bytes per row
#define STAGES 4
// plain: A 128x64 fp16 (16KB) + B 256x64 (32KB); gateup: A 16KB + G 16KB + U 16KB
#define STAGE_B  49152
#define SMEM_TOTAL (STAGES * STAGE_B)  // 196608

// ---------------- scratch (device globals; allocation-free rule) ----------------
__device__ __half g_hnorm [(size_t)T_TOK * HID];
__device__ __half g_q     [(size_t)T_TOK * HID];
__device__ float  g_hidden[(size_t)T_TOK * HID];
__device__ __half g_hpost [(size_t)T_TOK * HID];
__device__ __half g_act   [(size_t)T_TOK * INTERD];
__device__ __half g_hWq   [(size_t)HID * HID];
__device__ __half g_hWo   [(size_t)HID * HID];
__device__ __half g_hWg   [(size_t)INTERD * HID];
__device__ __half g_hWu   [(size_t)INTERD * HID];
__device__ __half g_hWd   [(size_t)HID * INTERD];

// ---------------- PTX helpers ----------------
static __device__ __forceinline__ uint32_t s2u(const void* p) {
    uint32_t a;
    asm("{ .reg .u64 t; cvta.to.shared.u64 t, %1; cvt.u32.u64 %0, t; }" : "=r"(a) : "l"(p));
    return a;
}
static __device__ __forceinline__ void cpa16(uint32_t s, const void* g) {
    asm volatile("cp.async.cg.shared.global [%0], [%1], 16;" :: "r"(s), "l"(g));
}
static __device__ __forceinline__ void ldsm4(uint32_t& r0, uint32_t& r1,
                                             uint32_t& r2, uint32_t& r3, uint32_t addr) {
    asm volatile("ldmatrix.sync.aligned.m8n8.x4.shared.b16 {%0,%1,%2,%3}, [%4];"
                 : "=r"(r0), "=r"(r1), "=r"(r2), "=r"(r3) : "r"(addr));
}
static __device__ __forceinline__ void mma_f16(float* c, const uint32_t* a,
                                               uint32_t b0, uint32_t b1) {
    asm volatile(
        "mma.sync.aligned.m16n8k16.row.col.f32.f16.f16.f32 "
        "{%0,%1,%2,%3}, {%4,%5,%6,%7}, {%8,%9}, {%0,%1,%2,%3};"
        : "+f"(c[0]), "+f"(c[1]), "+f"(c[2]), "+f"(c[3])
        : "r"(a[0]), "r"(a[1]), "r"(a[2]), "r"(a[3]), "r"(b0), "r"(b1));
}
static __device__ __forceinline__ uint32_t sw128(uint32_t off) {
    return off ^ ((off >> 3) & 0x70);
}

// ---------------- RMSNorm (fp32 in, fp16-RNE out) ----------------
__global__ __launch_bounds__(256) void rmsnorm_kernel(
    const float* __restrict__ x, const float* __restrict__ w, __half* __restrict__ out)
{
    long row = blockIdx.x;
    const float4* xr = (const float4*)(x + row * (long)HID);
    const float4* wr = (const float4*)w;
    __half2* orow = (__half2*)(out + row * (long)HID);
    int tid = threadIdx.x;

    float4 v0 = xr[tid];
    float4 v1 = xr[tid + 256];
    float ss = v0.x*v0.x + v0.y*v0.y + v0.z*v0.z + v0.w*v0.w
             + v1.x*v1.x + v1.y*v1.y + v1.z*v1.z + v1.w*v1.w;

    #pragma unroll
    for (int off = 16; off > 0; off >>= 1)
        ss += __shfl_xor_sync(0xffffffffu, ss, off);

    __shared__ float warp_ss[8];
    __shared__ float s_scale;
    int lane = tid & 31, wid = tid >> 5;
    if (lane == 0) warp_ss[wid] = ss;
    __syncthreads();
    if (tid == 0) {
        float tot = 0.f;
        #pragma unroll
        for (int i = 0; i < 8; i++) tot += warp_ss[i];
        s_scale = rsqrtf(tot / (float)HID + EPS);
    }
    __syncthreads();
    float scale = s_scale;

    float4 w0 = wr[tid];
    float4 w1 = wr[tid + 256];
    orow[2*tid]       = __floats2half2_rn(v0.x * scale * w0.x, v0.y * scale * w0.y);
    orow[2*tid + 1]   = __floats2half2_rn(v0.z * scale * w0.z, v0.w * scale * w0.w);
    orow[2*tid + 512] = __floats2half2_rn(v1.x * scale * w1.x, v1.y * scale * w1.y);
    orow[2*tid + 513] = __floats2half2_rn(v1.z * scale * w1.z, v1.w * scale * w1.w);
}

// ---------------- fp32 -> fp16(RNE) elementwise ----------------
__global__ __launch_bounds__(256) void to_f16_kernel(
    const float4* __restrict__ s, uint2* __restrict__ d, long n4)
{
    long i = (long)blockIdx.x * blockDim.x + threadIdx.x;
    long stride = (long)gridDim.x * blockDim.x;
    for (; i < n4; i += stride) {
        float4 v = s[i];
        __half2 lo = __floats2half2_rn(v.x, v.y);
        __half2 hi = __floats2half2_rn(v.z, v.w);
        uint2 o;
        o.x = *(uint32_t*)&lo;
        o.y = *(uint32_t*)&hi;
        d[i] = o;
    }
}

// ---------------- plain GEMM: C[M,N] = A @ W^T (+R), mma.sync fp16 ----------------
// CTA tile 128x256, BK=64, 4-slot/3-inflight cp.async, single sync per iter,
// 8 warps (2M x 4N), warp tile 64x64, kk-level fragment double buffering.
// EPI 0: C(half) = rn(A@W^T);  EPI 1: C(float) = R + A@W^T
template<int EPI>
__global__ __launch_bounds__(256, 1) void gemm_mma(
    const __half* __restrict__ A, const __half* __restrict__ W,
    const float* __restrict__ R, void* __restrict__ Cv, int K, int N)
{
    extern __shared__ __align__(1024) char smem[];
    uint32_t sb = s2u(smem);
    int tid = threadIdx.x;
    int lane = tid & 31, w = tid >> 5;
    int wm = w >> 2;      // 0..1  (64-row slice)
    int wn = w & 3;       // 0..3  (64-col slice)
    size_t row0 = (size_t)blockIdx.x * 128;
    size_t col0 = (size_t)blockIdx.y * 256;
    const int NK = K / BK;

    const __half* Abase = A + row0 * (size_t)K;
    const __half* Wbase = W + col0 * (size_t)K;

    auto load_stage = [&](int slot, int j) {
        uint32_t ab = sb + (uint32_t)slot * STAGE_B;
        uint32_t bb = ab + 16384;
        int kt = j * BK;
        #pragma unroll
        for (int p = 0; p < 4; p++) {
            int idx = p * 256 + tid;
            int r = idx >> 3, c = idx & 7;   // 8 x 16B chunks per 128B row
            cpa16(ab + sw128((r << 7) + (c << 4)),
                  (const char*)(Abase + (size_t)r * K + kt) + (c << 4));
        }
        #pragma unroll
        for (int p = 0; p < 8; p++) {
            int idx = p * 256 + tid;
            int r = idx >> 3, c = idx & 7;
            cpa16(bb + sw128((r << 7) + (c << 4)),
                  (const char*)(Wbase + (size_t)r * K + kt) + (c << 4));
        }
    };

    // per-kk fragment loaders (kk = 0..3 within a stage)
    auto load_afr = [&](uint32_t ab, int kk, uint32_t af[4][4]) {
        #pragma unroll
        for (int mi = 0; mi < 4; mi++) {
            uint32_t off = (uint32_t)((wm * 64 + mi * 16 + (lane & 15)) << 7)
                         + (uint32_t)((kk << 5) + ((lane >> 4) << 4));
            ldsm4(af[mi][0], af[mi][1], af[mi][2], af[mi][3], ab + sw128(off));
        }
    };
    auto load_bfr = [&](uint32_t bb, int kk, uint32_t bf[8][2]) {
        #pragma unroll
        for (int bi = 0; bi < 4; bi++) {
            uint32_t off = (uint32_t)((wn * 64 + bi * 16 + ((lane >> 4) << 3) + (lane & 7)) << 7)
                         + (uint32_t)((kk << 5) + (((lane >> 3) & 1) << 4));
            ldsm4(bf[2*bi][0], bf[2*bi][1], bf[2*bi+1][0], bf[2*bi+1][1], bb + sw128(off));
        }
    };

    float acc[4][8][4];
    #pragma unroll
    for (int i = 0; i < 4; i++)
        #pragma unroll
        for (int jx = 0; jx < 8; jx++)
            #pragma unroll
            for (int e = 0; e < 4; e++) acc[i][jx][e] = 0.f;

    // prologue: fill 3 stages
    #pragma unroll
    for (int p = 0; p < STAGES - 1; p++) {
        load_stage(p, p);
        asm volatile("cp.async.commit_group;");
    }

    for (int j = 0; j < NK; j++) {
        asm volatile("cp.async.wait_group %0;" :: "n"(STAGES - 2));
        __syncthreads();
        // issue next stage's loads before compute (slot (j+3)%4 freed by last iter's sync)
        if (j + STAGES - 1 < NK) load_stage((j + STAGES - 1) & 3, j + STAGES - 1);
        asm volatile("cp.async.commit_group;");

        int slot = j & 3;
        uint32_t ab = sb + (uint32_t)slot * STAGE_B;
        uint32_t bb = ab + 16384;

        uint32_t afr[2][4][4], bfr[2][8][2];
        load_afr(ab, 0, afr[0]);
        load_bfr(bb, 0, bfr[0]);
        #pragma unroll
        for (int kk = 0; kk < 4; kk++) {   // 4 x k16 = BK 64
            if (kk < 3) {
                load_afr(ab, kk + 1, afr[(kk + 1) & 1]);
                load_bfr(bb, kk + 1, bfr[(kk + 1) & 1]);
            }
            #pragma unroll
            for (int mi = 0; mi < 4; mi++)
                #pragma unroll
                for (int nj = 0; nj < 8; nj++)
                    mma_f16(acc[mi][nj], afr[kk & 1][mi], bfr[kk & 1][nj][0], bfr[kk & 1][nj][1]);
        }
        __syncthreads();
    }

    // epilogue
    #pragma unroll
    for (int mi = 0; mi < 4; mi++) {
        size_t r = row0 + wm * 64 + mi * 16 + (lane >> 2);
        #pragma unroll
        for (int nj = 0; nj < 8; nj++) {
            size_t c = col0 + wn * 64 + nj * 8 + 2 * (lane & 3);
            if (EPI == 1) {
                float* C = (float*)Cv;
                const float2 r0 = *(const float2*)(R + r * (size_t)N + c);
                const float2 r1 = *(const float2*)(R + (r + 8) * (size_t)N + c);
                float2 v0 = make_float2(acc[mi][nj][0] + r0.x, acc[mi][nj][1] + r0.y);
                float2 v1 = make_float2(acc[mi][nj][2] + r1.x, acc[mi][nj][3] + r1.y);
                *(float2*)(C + r * (size_t)N + c) = v0;
                *(float2*)(C + (r + 8) * (size_t)N + c) = v1;
            } else {
                __half2* C = (__half2*)Cv;
                C[(r * (size_t)N + c) >> 1]       = __floats2half2_rn(acc[mi][nj][0], acc[mi][nj][1]);
                C[((r + 8) * (size_t)N + c) >> 1] = __floats2half2_rn(acc[mi][nj][2], acc[mi][nj][3]);
            }
        }
    }
}

// ---------------- fused gate/up GEMM: act(half) = rn(silu(A@Wg^T) * (A@Wu^T)) ----------------
// CTA tile 128(M) x 128(inter), 8 warps (2M x 4N), warp tile 64 x 32 of BOTH g and u
// (A frags shared by g and u => 8KB smem reads per warp per kk, 256KB per iter).
// Last inter-tile ragged (10944 = 85*128 + 64): predicated loads + stores.
__global__ __launch_bounds__(256, 1) void gemm_gateup_mma(
    const __half* __restrict__ A, const __half* __restrict__ Wg,
    const __half* __restrict__ Wu, __half* __restrict__ C, int K, int N)
{
    extern __shared__ __align__(1024) char smem[];
    uint32_t sb = s2u(smem);
    int tid = threadIdx.x;
    int lane = tid & 31, w = tid >> 5;
    int wm = w >> 2;      // 0..1 (64-row slice)
    int wn = w & 3;       // 0..3 (32-col slice)
    size_t row0 = (size_t)blockIdx.x * 128;
    size_t col0 = (size_t)blockIdx.y * 128;
    const int NK = K / BK;

    const __half* Abase = A + row0 * (size_t)K;
    const __half* Gbase = Wg + col0 * (size_t)K;
    const __half* Ubase = Wu + col0 * (size_t)K;
    int nvalid = (int)((size_t)N - col0 < 128 ? (size_t)N - col0 : 128);

    auto load_stage = [&](int slot, int j) {
        uint32_t ab = sb + (uint32_t)slot * STAGE_B;
        uint32_t gb = ab + 16384;
        uint32_t ub = gb + 16384;
        int kt = j * BK;
        #pragma unroll
        for (int p = 0; p < 4; p++) {
            int idx = p * 256 + tid;
            int r = idx >> 3, c = idx & 7;
            cpa16(ab + sw128((r << 7) + (c << 4)),
                  (const char*)(Abase + (size_t)r * K + kt) + (c << 4));
        }
        #pragma unroll
        for (int p = 0; p < 4; p++) {
            int idx = p * 256 + tid;
            int r = idx >> 3, c = idx & 7;
            if (r < nvalid) {
                uint32_t swo = sw128((r << 7) + (c << 4));
                cpa16(gb + swo, (const char*)(Gbase + (size_t)r * K + kt) + (c << 4));
                cpa16(ub + swo, (const char*)(Ubase + (size_t)r * K + kt) + (c << 4));
            }
        }
    };

    auto load_afr = [&](uint32_t ab, int kk, uint32_t af[4][4]) {
        #pragma unroll
        for (int mi = 0; mi < 4; mi++) {
            uint32_t off = (uint32_t)((wm * 64 + mi * 16 + (lane & 15)) << 7)
                         + (uint32_t)((kk << 5) + ((lane >> 4) << 4));
            ldsm4(af[mi][0], af[mi][1], af[mi][2], af[mi][3], ab + sw128(off));
        }
    };
    auto load_wfr = [&](uint32_t wb, int kk, uint32_t wf[4][2]) {
        #pragma unroll
        for (int bi = 0; bi < 2; bi++) {
            uint32_t off = (uint32_t)((wn * 32 + bi * 16 + ((lane >> 4) << 3) + (lane & 7)) << 7)
                         + (uint32_t)((kk << 5) + (((lane >> 3) & 1) << 4));
            ldsm4(wf[2*bi][0], wf[2*bi][1], wf[2*bi+1][0], wf[2*bi+1][1], wb + sw128(off));
        }
    };

    float accg[4][4][4], accu[4][4][4];
    #pragma unroll
    for (int i = 0; i < 4; i++)
        #pragma unroll
        for (int jx = 0; jx < 4; jx++)
            #pragma unroll
            for (int e = 0; e < 4; e++) { accg[i][jx][e] = 0.f; accu[i][jx][e] = 0.f; }

    #pragma unroll
    for (int p = 0; p < STAGES - 1; p++) {
        load_stage(p, p);
        asm volatile("cp.async.commit_group;");
    }

    for (int j = 0; j < NK; j++) {
        asm volatile("cp.async.wait_group %0;" :: "n"(STAGES - 2));
        __syncthreads();
        if (j + STAGES - 1 < NK) load_stage((j + STAGES - 1) & 3, j + STAGES - 1);
        asm volatile("cp.async.commit_group;");

        int slot = j & 3;
        uint32_t ab = sb + (uint32_t)slot * STAGE_B;
        uint32_t gb = ab + 16384;
        uint32_t ub = gb + 16384;

        uint32_t afr[2][4][4], gfr[2][4][2], ufr[2][4][2];
        load_afr(ab, 0, afr[0]);
        load_wfr(gb, 0, gfr[0]);
        load_wfr(ub, 0, ufr[0]);
        #pragma unroll
        for (int kk = 0; kk < 4; kk++) {
            if (kk < 3) {
                load_afr(ab, kk + 1, afr[(kk + 1) & 1]);
                load_wfr(gb, kk + 1, gfr[(kk + 1) & 1]);
                load_wfr(ub, kk + 1, ufr[(kk + 1) & 1]);
            }
            #pragma unroll
            for (int mi = 0; mi < 4; mi++)
                #pragma unroll
                for (int nj = 0; nj < 4; nj++) {
                    mma_f16(accg[mi][nj], afr[kk & 1][mi], gfr[kk & 1][nj][0], gfr[kk & 1][nj][1]);
                    mma_f16(accu[mi][nj], afr[kk & 1][mi], ufr[kk & 1][nj][0], ufr[kk & 1][nj][1]);
                }
        }
        __syncthreads();
    }

    // epilogue: silu(gate) * up -> fp16, predicated on N
    #pragma unroll
    for (int mi = 0; mi < 4; mi++) {
        size_t r = row0 + wm * 64 + mi * 16 + (lane >> 2);
        #pragma unroll
        for (int nj = 0; nj < 4; nj++) {
            size_t c = col0 + wn * 32 + nj * 8 + 2 * (lane & 3);
            if (c < (size_t)N) {
                float gx = accg[mi][nj][0], ux = accu[mi][nj][0];
                float gy = accg[mi][nj][1], uy = accu[mi][nj][1];
                float gz = accg[mi][nj][2], uz = accu[mi][nj][2];
                float gw = accg[mi][nj][3], uw = accu[mi][nj][3];
                __half2 v0 = __floats2half2_rn(gx / (1.f + expf(-gx)) * ux,
                                               gy / (1.f + expf(-gy)) * uy);
                __half2 v1 = __floats2half2_rn(gz / (1.f + expf(-gz)) * uz,
                                               gw / (1.f + expf(-gw)) * uw);
                *(__half2*)(C + r * (size_t)N + c) = v0;
                *(__half2*)(C + (r + 8) * (size_t)N + c) = v1;
            }
        }
    }
}

// ---------------- launch ----------------
extern "C" void kernel_launch(void* const* d_in, const int* in_sizes, int n_in,
                              void* d_out, int out_size)
{
    const float* x      = (const float*)d_in[0];
    const float* in_w   = (const float*)d_in[2];
    const float* post_w = (const float*)d_in[3];
    const float* Wq     = (const float*)d_in[4];
    const float* Wo     = (const float*)d_in[5];
    const float* Wg     = (const float*)d_in[6];
    const float* Wu     = (const float*)d_in[7];
    const float* Wd     = (const float*)d_in[8];
    float* out = (float*)d_out;

    __half *hnorm, *q, *hpost, *act, *hWq, *hWo, *hWg, *hWu, *hWd;
    float *hidden;
    cudaGetSymbolAddress((void**)&hnorm,  g_hnorm);
    cudaGetSymbolAddress((void**)&q,      g_q);
    cudaGetSymbolAddress((void**)&hidden, g_hidden);
    cudaGetSymbolAddress((void**)&hpost,  g_hpost);
    cudaGetSymbolAddress((void**)&act,    g_act);
    cudaGetSymbolAddress((void**)&hWq,    g_hWq);
    cudaGetSymbolAddress((void**)&hWo,    g_hWo);
    cudaGetSymbolAddress((void**)&hWg,    g_hWg);
    cudaGetSymbolAddress((void**)&hWu,    g_hWu);
    cudaGetSymbolAddress((void**)&hWd,    g_hWd);

    static bool attr_done = false;
    if (!attr_done) {
        cudaFuncSetAttribute(gemm_mma<0>, cudaFuncAttributeMaxDynamicSharedMemorySize, SMEM_TOTAL);
        cudaFuncSetAttribute(gemm_mma<1>, cudaFuncAttributeMaxDynamicSharedMemorySize, SMEM_TOTAL);
        cudaFuncSetAttribute(gemm_gateup_mma, cudaFuncAttributeMaxDynamicSharedMemorySize, SMEM_TOTAL);
        attr_done = true;
    }

    // weights -> fp16 (RNE) scratch copies
    const int CB = 1184;
    to_f16_kernel<<<CB, 256>>>((const float4*)Wq, (uint2*)hWq, (long)HID * HID / 4);
    to_f16_kernel<<<CB, 256>>>((const float4*)Wo, (uint2*)hWo, (long)HID * HID / 4);
    to_f16_kernel<<<CB, 256>>>((const float4*)Wg, (uint2*)hWg, (long)INTERD * HID / 4);
    to_f16_kernel<<<CB, 256>>>((const float4*)Wu, (uint2*)hWu, (long)INTERD * HID / 4);
    to_f16_kernel<<<CB, 256>>>((const float4*)Wd, (uint2*)hWd, (long)HID * INTERD / 4);

    // 1. h_norm = rn(rmsnorm(x) * in_w)
    rmsnorm_kernel<<<T_TOK, 256>>>(x, in_w, hnorm);
    // 2. q = rn(h_norm @ Wq^T)
    gemm_mma<0><<<dim3(T_TOK/128, HID/256), 256, SMEM_TOTAL>>>(hnorm, hWq, nullptr, q, HID, HID);
    // 3. hidden = x + q @ Wo^T
    gemm_mma<1><<<dim3(T_TOK/128, HID/256), 256, SMEM_TOTAL>>>(q, hWo, x, hidden, HID, HID);
    // 4. h_post = rn(rmsnorm(hidden) * post_w)
    rmsnorm_kernel<<<T_TOK, 256>>>(hidden, post_w, hpost);
    // 5. act = rn(silu(h_post @ Wg^T) * (h_post @ Wu^T))   [86 tiles, last ragged 64]
    gemm_gateup_mma<<<dim3(T_TOK/128, (INTERD + 127)/128), 256, SMEM_TOTAL>>>(hpost, hWg, hWu, act, HID, INTERD);
    // 6. out = hidden + act @ Wd^T
    gemm_mma<1><<<dim3(T_TOK/128, HID/256), 256, SMEM_TOTAL>>>(act, hWd, hidden, out, INTERD, HID);
}

// round 8
// speedup vs baseline: 8.2240x; 1.0087x over previous
#include <cuda_runtime.h>
#include <cuda_fp16.h>
#include <cstdint>
#include <math.h>

#define T_TOK  4096
#define HID    2048
#define INTERD 10944
#define EPS    1e-6f

#define BK 64            // 64 halves = 128 bytes per row
#define STAGES 4
// plain: A 128x64 fp16 (16KB) + B 256x64 (32KB); gateup: A 16KB + G 16KB + U 16KB
#define STAGE_B  49152
#define SMEM_TOTAL (STAGES * STAGE_B)  // 196608

#define NTHREADS 512

// ---------------- scratch (device globals; allocation-free rule) ----------------
__device__ __half g_hnorm [(size_t)T_TOK * HID];
__device__ __half g_q     [(size_t)T_TOK * HID];
__device__ float  g_hidden[(size_t)T_TOK * HID];
__device__ __half g_hpost [(size_t)T_TOK * HID];
__device__ __half g_act   [(size_t)T_TOK * INTERD];
__device__ __half g_hWq   [(size_t)HID * HID];
__device__ __half g_hWo   [(size_t)HID * HID];
__device__ __half g_hWg   [(size_t)INTERD * HID];
__device__ __half g_hWu   [(size_t)INTERD * HID];
__device__ __half g_hWd   [(size_t)HID * INTERD];

// ---------------- PTX helpers ----------------
static __device__ __forceinline__ uint32_t s2u(const void* p) {
    uint32_t a;
    asm("{ .reg .u64 t; cvta.to.shared.u64 t, %1; cvt.u32.u64 %0, t; }" : "=r"(a) : "l"(p));
    return a;
}
static __device__ __forceinline__ void cpa16(uint32_t s, const void* g) {
    asm volatile("cp.async.cg.shared.global [%0], [%1], 16;" :: "r"(s), "l"(g));
}
static __device__ __forceinline__ void ldsm4(uint32_t& r0, uint32_t& r1,
                                             uint32_t& r2, uint32_t& r3, uint32_t addr) {
    asm volatile("ldmatrix.sync.aligned.m8n8.x4.shared.b16 {%0,%1,%2,%3}, [%4];"
                 : "=r"(r0), "=r"(r1), "=r"(r2), "=r"(r3) : "r"(addr));
}
static __device__ __forceinline__ void mma_f16(float* c, const uint32_t* a,
                                               uint32_t b0, uint32_t b1) {
    asm volatile(
        "mma.sync.aligned.m16n8k16.row.col.f32.f16.f16.f32 "
        "{%0,%1,%2,%3}, {%4,%5,%6,%7}, {%8,%9}, {%0,%1,%2,%3};"
        : "+f"(c[0]), "+f"(c[1]), "+f"(c[2]), "+f"(c[3])
        : "r"(a[0]), "r"(a[1]), "r"(a[2]), "r"(a[3]), "r"(b0), "r"(b1));
}
static __device__ __forceinline__ uint32_t sw128(uint32_t off) {
    return off ^ ((off >> 3) & 0x70);
}

// ---------------- RMSNorm (fp32 in, fp16-RNE out) ----------------
__global__ __launch_bounds__(256) void rmsnorm_kernel(
    const float* __restrict__ x, const float* __restrict__ w, __half* __restrict__ out)
{
    long row = blockIdx.x;
    const float4* xr = (const float4*)(x + row * (long)HID);
    const float4* wr = (const float4*)w;
    __half2* orow = (__half2*)(out + row * (long)HID);
    int tid = threadIdx.x;

    float4 v0 = xr[tid];
    float4 v1 = xr[tid + 256];
    float ss = v0.x*v0.x + v0.y*v0.y + v0.z*v0.z + v0.w*v0.w
             + v1.x*v1.x + v1.y*v1.y + v1.z*v1.z + v1.w*v1.w;

    #pragma unroll
    for (int off = 16; off > 0; off >>= 1)
        ss += __shfl_xor_sync(0xffffffffu, ss, off);

    __shared__ float warp_ss[8];
    __shared__ float s_scale;
    int lane = tid & 31, wid = tid >> 5;
    if (lane == 0) warp_ss[wid] = ss;
    __syncthreads();
    if (tid == 0) {
        float tot = 0.f;
        #pragma unroll
        for (int i = 0; i < 8; i++) tot += warp_ss[i];
        s_scale = rsqrtf(tot / (float)HID + EPS);
    }
    __syncthreads();
    float scale = s_scale;

    float4 w0 = wr[tid];
    float4 w1 = wr[tid + 256];
    orow[2*tid]       = __floats2half2_rn(v0.x * scale * w0.x, v0.y * scale * w0.y);
    orow[2*tid + 1]   = __floats2half2_rn(v0.z * scale * w0.z, v0.w * scale * w0.w);
    orow[2*tid + 512] = __floats2half2_rn(v1.x * scale * w1.x, v1.y * scale * w1.y);
    orow[2*tid + 513] = __floats2half2_rn(v1.z * scale * w1.z, v1.w * scale * w1.w);
}

// ---------------- fp32 -> fp16(RNE) elementwise ----------------
__global__ __launch_bounds__(256) void to_f16_kernel(
    const float4* __restrict__ s, uint2* __restrict__ d, long n4)
{
    long i = (long)blockIdx.x * blockDim.x + threadIdx.x;
    long stride = (long)gridDim.x * blockDim.x;
    for (; i < n4; i += stride) {
        float4 v = s[i];
        __half2 lo = __floats2half2_rn(v.x, v.y);
        __half2 hi = __floats2half2_rn(v.z, v.w);
        uint2 o;
        o.x = *(uint32_t*)&lo;
        o.y = *(uint32_t*)&hi;
        d[i] = o;
    }
}

// ---------------- plain GEMM: C[M,N] = A @ W^T (+R), mma.sync fp16 ----------------
// CTA tile 128x256, BK=64, 4-slot/3-inflight cp.async, single sync per iter,
// 16 warps (4M x 4N), warp tile 32x64, kk-level fragment double buffering.
// EPI 0: C(half) = rn(A@W^T);  EPI 1: C(float) = R + A@W^T
template<int EPI>
__global__ __launch_bounds__(NTHREADS, 1) void gemm_mma(
    const __half* __restrict__ A, const __half* __restrict__ W,
    const float* __restrict__ R, void* __restrict__ Cv, int K, int N)
{
    extern __shared__ __align__(1024) char smem[];
    uint32_t sb = s2u(smem);
    int tid = threadIdx.x;
    int lane = tid & 31, w = tid >> 5;
    int wm = w >> 2;      // 0..3  (32-row slice)
    int wn = w & 3;       // 0..3  (64-col slice)
    size_t row0 = (size_t)blockIdx.x * 128;
    size_t col0 = (size_t)blockIdx.y * 256;
    const int NK = K / BK;

    const __half* Abase = A + row0 * (size_t)K;
    const __half* Wbase = W + col0 * (size_t)K;

    auto load_stage = [&](int slot, int j) {
        uint32_t ab = sb + (uint32_t)slot * STAGE_B;
        uint32_t bb = ab + 16384;
        int kt = j * BK;
        #pragma unroll
        for (int p = 0; p < 2; p++) {
            int idx = p * NTHREADS + tid;
            int r = idx >> 3, c = idx & 7;   // 8 x 16B chunks per 128B row
            cpa16(ab + sw128((r << 7) + (c << 4)),
                  (const char*)(Abase + (size_t)r * K + kt) + (c << 4));
        }
        #pragma unroll
        for (int p = 0; p < 4; p++) {
            int idx = p * NTHREADS + tid;
            int r = idx >> 3, c = idx & 7;
            cpa16(bb + sw128((r << 7) + (c << 4)),
                  (const char*)(Wbase + (size_t)r * K + kt) + (c << 4));
        }
    };

    // per-kk fragment loaders (kk = 0..3 within a stage)
    auto load_afr = [&](uint32_t ab, int kk, uint32_t af[2][4]) {
        #pragma unroll
        for (int mi = 0; mi < 2; mi++) {
            uint32_t off = (uint32_t)((wm * 32 + mi * 16 + (lane & 15)) << 7)
                         + (uint32_t)((kk << 5) + ((lane >> 4) << 4));
            ldsm4(af[mi][0], af[mi][1], af[mi][2], af[mi][3], ab + sw128(off));
        }
    };
    auto load_bfr = [&](uint32_t bb, int kk, uint32_t bf[8][2]) {
        #pragma unroll
        for (int bi = 0; bi < 4; bi++) {
            uint32_t off = (uint32_t)((wn * 64 + bi * 16 + ((lane >> 4) << 3) + (lane & 7)) << 7)
                         + (uint32_t)((kk << 5) + (((lane >> 3) & 1) << 4));
            ldsm4(bf[2*bi][0], bf[2*bi][1], bf[2*bi+1][0], bf[2*bi+1][1], bb + sw128(off));
        }
    };

    float acc[2][8][4];
    #pragma unroll
    for (int i = 0; i < 2; i++)
        #pragma unroll
        for (int jx = 0; jx < 8; jx++)
            #pragma unroll
            for (int e = 0; e < 4; e++) acc[i][jx][e] = 0.f;

    // prologue: fill 3 stages
    #pragma unroll
    for (int p = 0; p < STAGES - 1; p++) {
        load_stage(p, p);
        asm volatile("cp.async.commit_group;");
    }

    for (int j = 0; j < NK; j++) {
        asm volatile("cp.async.wait_group %0;" :: "n"(STAGES - 2));
        __syncthreads();
        // issue next stage's loads before compute (slot (j+3)%4 freed by last iter's sync)
        if (j + STAGES - 1 < NK) load_stage((j + STAGES - 1) & 3, j + STAGES - 1);
        asm volatile("cp.async.commit_group;");

        int slot = j & 3;
        uint32_t ab = sb + (uint32_t)slot * STAGE_B;
        uint32_t bb = ab + 16384;

        uint32_t afr[2][2][4], bfr[2][8][2];
        load_afr(ab, 0, afr[0]);
        load_bfr(bb, 0, bfr[0]);
        #pragma unroll
        for (int kk = 0; kk < 4; kk++) {   // 4 x k16 = BK 64
            if (kk < 3) {
                load_afr(ab, kk + 1, afr[(kk + 1) & 1]);
                load_bfr(bb, kk + 1, bfr[(kk + 1) & 1]);
            }
            #pragma unroll
            for (int mi = 0; mi < 2; mi++)
                #pragma unroll
                for (int nj = 0; nj < 8; nj++)
                    mma_f16(acc[mi][nj], afr[kk & 1][mi], bfr[kk & 1][nj][0], bfr[kk & 1][nj][1]);
        }
        __syncthreads();
    }

    // epilogue
    #pragma unroll
    for (int mi = 0; mi < 2; mi++) {
        size_t r = row0 + wm * 32 + mi * 16 + (lane >> 2);
        #pragma unroll
        for (int nj = 0; nj < 8; nj++) {
            size_t c = col0 + wn * 64 + nj * 8 + 2 * (lane & 3);
            if (EPI == 1) {
                float* C = (float*)Cv;
                const float2 r0 = *(const float2*)(R + r * (size_t)N + c);
                const float2 r1 = *(const float2*)(R + (r + 8) * (size_t)N + c);
                float2 v0 = make_float2(acc[mi][nj][0] + r0.x, acc[mi][nj][1] + r0.y);
                float2 v1 = make_float2(acc[mi][nj][2] + r1.x, acc[mi][nj][3] + r1.y);
                *(float2*)(C + r * (size_t)N + c) = v0;
                *(float2*)(C + (r + 8) * (size_t)N + c) = v1;
            } else {
                __half2* C = (__half2*)Cv;
                C[(r * (size_t)N + c) >> 1]       = __floats2half2_rn(acc[mi][nj][0], acc[mi][nj][1]);
                C[((r + 8) * (size_t)N + c) >> 1] = __floats2half2_rn(acc[mi][nj][2], acc[mi][nj][3]);
            }
        }
    }
}

// ---------------- fused gate/up GEMM: act(half) = rn(silu(A@Wg^T) * (A@Wu^T)) ----------------
// CTA tile 128(M) x 128(inter), 16 warps (4M x 4N), warp tile 32 x 32 of BOTH g and u
// (A frags shared by g and u). Last inter-tile ragged (10944 = 85*128 + 64):
// predicated loads + stores.
__global__ __launch_bounds__(NTHREADS, 1) void gemm_gateup_mma(
    const __half* __restrict__ A, const __half* __restrict__ Wg,
    const __half* __restrict__ Wu, __half* __restrict__ C, int K, int N)
{
    extern __shared__ __align__(1024) char smem[];
    uint32_t sb = s2u(smem);
    int tid = threadIdx.x;
    int lane = tid & 31, w = tid >> 5;
    int wm = w >> 2;      // 0..3 (32-row slice)
    int wn = w & 3;       // 0..3 (32-col slice)
    size_t row0 = (size_t)blockIdx.x * 128;
    size_t col0 = (size_t)blockIdx.y * 128;
    const int NK = K / BK;

    const __half* Abase = A + row0 * (size_t)K;
    const __half* Gbase = Wg + col0 * (size_t)K;
    const __half* Ubase = Wu + col0 * (size_t)K;
    int nvalid = (int)((size_t)N - col0 < 128 ? (size_t)N - col0 : 128);

    auto load_stage = [&](int slot, int j) {
        uint32_t ab = sb + (uint32_t)slot * STAGE_B;
        uint32_t gb = ab + 16384;
        uint32_t ub = gb + 16384;
        int kt = j * BK;
        #pragma unroll
        for (int p = 0; p < 2; p++) {
            int idx = p * NTHREADS + tid;
            int r = idx >> 3, c = idx & 7;
            cpa16(ab + sw128((r << 7) + (c << 4)),
                  (const char*)(Abase + (size_t)r * K + kt) + (c << 4));
        }
        #pragma unroll
        for (int p = 0; p < 2; p++) {
            int idx = p * NTHREADS + tid;
            int r = idx >> 3, c = idx & 7;
            if (r < nvalid) {
                uint32_t swo = sw128((r << 7) + (c << 4));
                cpa16(gb + swo, (const char*)(Gbase + (size_t)r * K + kt) + (c << 4));
                cpa16(ub + swo, (const char*)(Ubase + (size_t)r * K + kt) + (c << 4));
            }
        }
    };

    auto load_afr = [&](uint32_t ab, int kk, uint32_t af[2][4]) {
        #pragma unroll
        for (int mi = 0; mi < 2; mi++) {
            uint32_t off = (uint32_t)((wm * 32 + mi * 16 + (lane & 15)) << 7)
                         + (uint32_t)((kk << 5) + ((lane >> 4) << 4));
            ldsm4(af[mi][0], af[mi][1], af[mi][2], af[mi][3], ab + sw128(off));
        }
    };
    auto load_wfr = [&](uint32_t wb, int kk, uint32_t wf[4][2]) {
        #pragma unroll
        for (int bi = 0; bi < 2; bi++) {
            uint32_t off = (uint32_t)((wn * 32 + bi * 16 + ((lane >> 4) << 3) + (lane & 7)) << 7)
                         + (uint32_t)((kk << 5) + (((lane >> 3) & 1) << 4));
            ldsm4(wf[2*bi][0], wf[2*bi][1], wf[2*bi+1][0], wf[2*bi+1][1], wb + sw128(off));
        }
    };

    float accg[2][4][4], accu[2][4][4];
    #pragma unroll
    for (int i = 0; i < 2; i++)
        #pragma unroll
        for (int jx = 0; jx < 4; jx++)
            #pragma unroll
            for (int e = 0; e < 4; e++) { accg[i][jx][e] = 0.f; accu[i][jx][e] = 0.f; }

    #pragma unroll
    for (int p = 0; p < STAGES - 1; p++) {
        load_stage(p, p);
        asm volatile("cp.async.commit_group;");
    }

    for (int j = 0; j < NK; j++) {
        asm volatile("cp.async.wait_group %0;" :: "n"(STAGES - 2));
        __syncthreads();
        if (j + STAGES - 1 < NK) load_stage((j + STAGES - 1) & 3, j + STAGES - 1);
        asm volatile("cp.async.commit_group;");

        int slot = j & 3;
        uint32_t ab = sb + (uint32_t)slot * STAGE_B;
        uint32_t gb = ab + 16384;
        uint32_t ub = gb + 16384;

        uint32_t afr[2][2][4], gfr[2][4][2], ufr[2][4][2];
        load_afr(ab, 0, afr[0]);
        load_wfr(gb, 0, gfr[0]);
        load_wfr(ub, 0, ufr[0]);
        #pragma unroll
        for (int kk = 0; kk < 4; kk++) {
            if (kk < 3) {
                load_afr(ab, kk + 1, afr[(kk + 1) & 1]);
                load_wfr(gb, kk + 1, gfr[(kk + 1) & 1]);
                load_wfr(ub, kk + 1, ufr[(kk + 1) & 1]);
            }
            #pragma unroll
            for (int mi = 0; mi < 2; mi++)
                #pragma unroll
                for (int nj = 0; nj < 4; nj++) {
                    mma_f16(accg[mi][nj], afr[kk & 1][mi], gfr[kk & 1][nj][0], gfr[kk & 1][nj][1]);
                    mma_f16(accu[mi][nj], afr[kk & 1][mi], ufr[kk & 1][nj][0], ufr[kk & 1][nj][1]);
                }
        }
        __syncthreads();
    }

    // epilogue: silu(gate) * up -> fp16, predicated on N
    #pragma unroll
    for (int mi = 0; mi < 2; mi++) {
        size_t r = row0 + wm * 32 + mi * 16 + (lane >> 2);
        #pragma unroll
        for (int nj = 0; nj < 4; nj++) {
            size_t c = col0 + wn * 32 + nj * 8 + 2 * (lane & 3);
            if (c < (size_t)N) {
                float gx = accg[mi][nj][0], ux = accu[mi][nj][0];
                float gy = accg[mi][nj][1], uy = accu[mi][nj][1];
                float gz = accg[mi][nj][2], uz = accu[mi][nj][2];
                float gw = accg[mi][nj][3], uw = accu[mi][nj][3];
                __half2 v0 = __floats2half2_rn(gx / (1.f + expf(-gx)) * ux,
                                               gy / (1.f + expf(-gy)) * uy);
                __half2 v1 = __floats2half2_rn(gz / (1.f + expf(-gz)) * uz,
                                               gw / (1.f + expf(-gw)) * uw);
                *(__half2*)(C + r * (size_t)N + c) = v0;
                *(__half2*)(C + (r + 8) * (size_t)N + c) = v1;
            }
        }
    }
}

// ---------------- launch ----------------
extern "C" void kernel_launch(void* const* d_in, const int* in_sizes, int n_in,
                              void* d_out, int out_size)
{
    const float* x      = (const float*)d_in[0];
    const float* in_w   = (const float*)d_in[2];
    const float* post_w = (const float*)d_in[3];
    const float* Wq     = (const float*)d_in[4];
    const float* Wo     = (const float*)d_in[5];
    const float* Wg     = (const float*)d_in[6];
    const float* Wu     = (const float*)d_in[7];
    const float* Wd     = (const float*)d_in[8];
    float* out = (float*)d_out;

    __half *hnorm, *q, *hpost, *act, *hWq, *hWo, *hWg, *hWu, *hWd;
    float *hidden;
    cudaGetSymbolAddress((void**)&hnorm,  g_hnorm);
    cudaGetSymbolAddress((void**)&q,      g_q);
    cudaGetSymbolAddress((void**)&hidden, g_hidden);
    cudaGetSymbolAddress((void**)&hpost,  g_hpost);
    cudaGetSymbolAddress((void**)&act,    g_act);
    cudaGetSymbolAddress((void**)&hWq,    g_hWq);
    cudaGetSymbolAddress((void**)&hWo,    g_hWo);
    cudaGetSymbolAddress((void**)&hWg,    g_hWg);
    cudaGetSymbolAddress((void**)&hWu,    g_hWu);
    cudaGetSymbolAddress((void**)&hWd,    g_hWd);

    static bool attr_done = false;
    if (!attr_done) {
        cudaFuncSetAttribute(gemm_mma<0>, cudaFuncAttributeMaxDynamicSharedMemorySize, SMEM_TOTAL);
        cudaFuncSetAttribute(gemm_mma<1>, cudaFuncAttributeMaxDynamicSharedMemorySize, SMEM_TOTAL);
        cudaFuncSetAttribute(gemm_gateup_mma, cudaFuncAttributeMaxDynamicSharedMemorySize, SMEM_TOTAL);
        attr_done = true;
    }

    // weights -> fp16 (RNE) scratch copies
    const int CB = 1184;
    to_f16_kernel<<<CB, 256>>>((const float4*)Wq, (uint2*)hWq, (long)HID * HID / 4);
    to_f16_kernel<<<CB, 256>>>((const float4*)Wo, (uint2*)hWo, (long)HID * HID / 4);
    to_f16_kernel<<<CB, 256>>>((const float4*)Wg, (uint2*)hWg, (long)INTERD * HID / 4);
    to_f16_kernel<<<CB, 256>>>((const float4*)Wu, (uint2*)hWu, (long)INTERD * HID / 4);
    to_f16_kernel<<<CB, 256>>>((const float4*)Wd, (uint2*)hWd, (long)HID * INTERD / 4);

    // 1. h_norm = rn(rmsnorm(x) * in_w)
    rmsnorm_kernel<<<T_TOK, 256>>>(x, in_w, hnorm);
    // 2. q = rn(h_norm @ Wq^T)
    gemm_mma<0><<<dim3(T_TOK/128, HID/256), NTHREADS, SMEM_TOTAL>>>(hnorm, hWq, nullptr, q, HID, HID);
    // 3. hidden = x + q @ Wo^T
    gemm_mma<1><<<dim3(T_TOK/128, HID/256), NTHREADS, SMEM_TOTAL>>>(q, hWo, x, hidden, HID, HID);
    // 4. h_post = rn(rmsnorm(hidden) * post_w)
    rmsnorm_kernel<<<T_TOK, 256>>>(hidden, post_w, hpost);
    // 5. act = rn(silu(h_post @ Wg^T) * (h_post @ Wu^T))   [86 tiles, last ragged 64]
    gemm_gateup_mma<<<dim3(T_TOK/128, (INTERD + 127)/128), NTHREADS, SMEM_TOTAL>>>(hpost, hWg, hWu, act, HID, INTERD);
    // 6. out = hidden + act @ Wd^T
    gemm_mma<1><<<dim3(T_TOK/128, HID/256), NTHREADS, SMEM_TOTAL>>>(act, hWd, hidden, out, INTERD, HID);
}

// round 9
// speedup vs baseline: 8.4455x; 1.0269x over previous
#include <cuda_runtime.h>
#include <cuda_fp16.h>
#include <cstdint>
#include <math.h>

#define T_TOK  4096
#define HID    2048
#define INTERD 10944
#define EPS    1e-6f

#define BK 64            // 64 halves = 128 bytes per row
#define STAGES 4
#define STAGE_B  49152
#define SMEM_TOTAL (STAGES * STAGE_B)  // 196608

#define NTHREADS 512

// ---------------- scratch (device globals; allocation-free rule) ----------------
__device__ __half g_hnorm [(size_t)T_TOK * HID];
__device__ float  g_hidden[(size_t)T_TOK * HID];
__device__ __half g_hpost [(size_t)T_TOK * HID];
__device__ __half g_act   [(size_t)T_TOK * INTERD];
__device__ __half g_hWqT  [(size_t)HID * HID];   // fp16(Wq)^T  [h_in, q]
__device__ __half g_hWo   [(size_t)HID * HID];
__device__ __half g_hWqo  [(size_t)HID * HID];   // fp16(Wo @ Wq) [h_out, h_in]
__device__ __half g_hWg   [(size_t)INTERD * HID];
__device__ __half g_hWu   [(size_t)INTERD * HID];
__device__ __half g_hWd   [(size_t)HID * INTERD];

// ---------------- PTX helpers ----------------
static __device__ __forceinline__ uint32_t s2u(const void* p) {
    uint32_t a;
    asm("{ .reg .u64 t; cvta.to.shared.u64 t, %1; cvt.u32.u64 %0, t; }" : "=r"(a) : "l"(p));
    return a;
}
static __device__ __forceinline__ void cpa16(uint32_t s, const void* g) {
    asm volatile("cp.async.cg.shared.global [%0], [%1], 16;" :: "r"(s), "l"(g));
}
static __device__ __forceinline__ void ldsm4(uint32_t& r0, uint32_t& r1,
                                             uint32_t& r2, uint32_t& r3, uint32_t addr) {
    asm volatile("ldmatrix.sync.aligned.m8n8.x4.shared.b16 {%0,%1,%2,%3}, [%4];"
                 : "=r"(r0), "=r"(r1), "=r"(r2), "=r"(r3) : "r"(addr));
}
static __device__ __forceinline__ void mma_f16(float* c, const uint32_t* a,
                                               uint32_t b0, uint32_t b1) {
    asm volatile(
        "mma.sync.aligned.m16n8k16.row.col.f32.f16.f16.f32 "
        "{%0,%1,%2,%3}, {%4,%5,%6,%7}, {%8,%9}, {%0,%1,%2,%3};"
        : "+f"(c[0]), "+f"(c[1]), "+f"(c[2]), "+f"(c[3])
        : "r"(a[0]), "r"(a[1]), "r"(a[2]), "r"(a[3]), "r"(b0), "r"(b1));
}
static __device__ __forceinline__ uint32_t sw128(uint32_t off) {
    return off ^ ((off >> 3) & 0x70);
}

// ---------------- RMSNorm (fp32 in, fp16-RNE out) ----------------
__global__ __launch_bounds__(256) void rmsnorm_kernel(
    const float* __restrict__ x, const float* __restrict__ w, __half* __restrict__ out)
{
    long row = blockIdx.x;
    const float4* xr = (const float4*)(x + row * (long)HID);
    const float4* wr = (const float4*)w;
    __half2* orow = (__half2*)(out + row * (long)HID);
    int tid = threadIdx.x;

    float4 v0 = xr[tid];
    float4 v1 = xr[tid + 256];
    float ss = v0.x*v0.x + v0.y*v0.y + v0.z*v0.z + v0.w*v0.w
             + v1.x*v1.x + v1.y*v1.y + v1.z*v1.z + v1.w*v1.w;

    #pragma unroll
    for (int off = 16; off > 0; off >>= 1)
        ss += __shfl_xor_sync(0xffffffffu, ss, off);

    __shared__ float warp_ss[8];
    __shared__ float s_scale;
    int lane = tid & 31, wid = tid >> 5;
    if (lane == 0) warp_ss[wid] = ss;
    __syncthreads();
    if (tid == 0) {
        float tot = 0.f;
        #pragma unroll
        for (int i = 0; i < 8; i++) tot += warp_ss[i];
        s_scale = rsqrtf(tot / (float)HID + EPS);
    }
    __syncthreads();
    float scale = s_scale;

    float4 w0 = wr[tid];
    float4 w1 = wr[tid + 256];
    orow[2*tid]       = __floats2half2_rn(v0.x * scale * w0.x, v0.y * scale * w0.y);
    orow[2*tid + 1]   = __floats2half2_rn(v0.z * scale * w0.z, v0.w * scale * w0.w);
    orow[2*tid + 512] = __floats2half2_rn(v1.x * scale * w1.x, v1.y * scale * w1.y);
    orow[2*tid + 513] = __floats2half2_rn(v1.z * scale * w1.z, v1.w * scale * w1.w);
}

// ---------------- fp32 -> fp16(RNE) elementwise ----------------
__global__ __launch_bounds__(256) void to_f16_kernel(
    const float4* __restrict__ s, uint2* __restrict__ d, long n4)
{
    long i = (long)blockIdx.x * blockDim.x + threadIdx.x;
    long stride = (long)gridDim.x * blockDim.x;
    for (; i < n4; i += stride) {
        float4 v = s[i];
        __half2 lo = __floats2half2_rn(v.x, v.y);
        __half2 hi = __floats2half2_rn(v.z, v.w);
        uint2 o;
        o.x = *(uint32_t*)&lo;
        o.y = *(uint32_t*)&hi;
        d[i] = o;
    }
}

// ---------------- fp32 [2048x2048] -> transposed fp16 ----------------
__global__ __launch_bounds__(256) void transpose_f16_kernel(
    const float* __restrict__ src, __half* __restrict__ dst)
{
    __shared__ float tile[32][33];
    int x = blockIdx.x * 32 + threadIdx.x;   // src col
    int y0 = blockIdx.y * 32 + threadIdx.y;  // src row
    #pragma unroll
    for (int i = 0; i < 32; i += 8)
        tile[threadIdx.y + i][threadIdx.x] = src[(size_t)(y0 + i) * HID + x];
    __syncthreads();
    int tx = blockIdx.y * 32 + threadIdx.x;  // dst col (= src row)
    int ty = blockIdx.x * 32 + threadIdx.y;  // dst row (= src col)
    #pragma unroll
    for (int i = 0; i < 32; i += 8)
        dst[(size_t)(ty + i) * HID + tx] = __float2half_rn(tile[threadIdx.x][threadIdx.y + i]);
}

// ---------------- plain GEMM: C[M,N] = A @ W^T (+R), mma.sync fp16 ----------------
// CTA tile 128x256, BK=64, 4-slot/3-inflight cp.async, single sync per iter,
// 16 warps (4M x 4N), warp tile 32x64, kk-level fragment double buffering.
// EPI 0: C(half) = rn(A@W^T);  EPI 1: C(float) = R + A@W^T
template<int EPI>
__global__ __launch_bounds__(NTHREADS, 1) void gemm_mma(
    const __half* __restrict__ A, const __half* __restrict__ W,
    const float* __restrict__ R, void* __restrict__ Cv, int K, int N)
{
    extern __shared__ __align__(1024) char smem[];
    uint32_t sb = s2u(smem);
    int tid = threadIdx.x;
    int lane = tid & 31, w = tid >> 5;
    int wm = w >> 2;      // 0..3  (32-row slice)
    int wn = w & 3;       // 0..3  (64-col slice)
    size_t row0 = (size_t)blockIdx.x * 128;
    size_t col0 = (size_t)blockIdx.y * 256;
    const int NK = K / BK;

    const __half* Abase = A + row0 * (size_t)K;
    const __half* Wbase = W + col0 * (size_t)K;

    auto load_stage = [&](int slot, int j) {
        uint32_t ab = sb + (uint32_t)slot * STAGE_B;
        uint32_t bb = ab + 16384;
        int kt = j * BK;
        #pragma unroll
        for (int p = 0; p < 2; p++) {
            int idx = p * NTHREADS + tid;
            int r = idx >> 3, c = idx & 7;   // 8 x 16B chunks per 128B row
            cpa16(ab + sw128((r << 7) + (c << 4)),
                  (const char*)(Abase + (size_t)r * K + kt) + (c << 4));
        }
        #pragma unroll
        for (int p = 0; p < 4; p++) {
            int idx = p * NTHREADS + tid;
            int r = idx >> 3, c = idx & 7;
            cpa16(bb + sw128((r << 7) + (c << 4)),
                  (const char*)(Wbase + (size_t)r * K + kt) + (c << 4));
        }
    };

    auto load_afr = [&](uint32_t ab, int kk, uint32_t af[2][4]) {
        #pragma unroll
        for (int mi = 0; mi < 2; mi++) {
            uint32_t off = (uint32_t)((wm * 32 + mi * 16 + (lane & 15)) << 7)
                         + (uint32_t)((kk << 5) + ((lane >> 4) << 4));
            ldsm4(af[mi][0], af[mi][1], af[mi][2], af[mi][3], ab + sw128(off));
        }
    };
    auto load_bfr = [&](uint32_t bb, int kk, uint32_t bf[8][2]) {
        #pragma unroll
        for (int bi = 0; bi < 4; bi++) {
            uint32_t off = (uint32_t)((wn * 64 + bi * 16 + ((lane >> 4) << 3) + (lane & 7)) << 7)
                         + (uint32_t)((kk << 5) + (((lane >> 3) & 1) << 4));
            ldsm4(bf[2*bi][0], bf[2*bi][1], bf[2*bi+1][0], bf[2*bi+1][1], bb + sw128(off));
        }
    };

    float acc[2][8][4];
    #pragma unroll
    for (int i = 0; i < 2; i++)
        #pragma unroll
        for (int jx = 0; jx < 8; jx++)
            #pragma unroll
            for (int e = 0; e < 4; e++) acc[i][jx][e] = 0.f;

    #pragma unroll
    for (int p = 0; p < STAGES - 1; p++) {
        load_stage(p, p);
        asm volatile("cp.async.commit_group;");
    }

    for (int j = 0; j < NK; j++) {
        asm volatile("cp.async.wait_group %0;" :: "n"(STAGES - 2));
        __syncthreads();
        if (j + STAGES - 1 < NK) load_stage((j + STAGES - 1) & 3, j + STAGES - 1);
        asm volatile("cp.async.commit_group;");

        int slot = j & 3;
        uint32_t ab = sb + (uint32_t)slot * STAGE_B;
        uint32_t bb = ab + 16384;

        uint32_t afr[2][2][4], bfr[2][8][2];
        load_afr(ab, 0, afr[0]);
        load_bfr(bb, 0, bfr[0]);
        #pragma unroll
        for (int kk = 0; kk < 4; kk++) {
            if (kk < 3) {
                load_afr(ab, kk + 1, afr[(kk + 1) & 1]);
                load_bfr(bb, kk + 1, bfr[(kk + 1) & 1]);
            }
            #pragma unroll
            for (int mi = 0; mi < 2; mi++)
                #pragma unroll
                for (int nj = 0; nj < 8; nj++)
                    mma_f16(acc[mi][nj], afr[kk & 1][mi], bfr[kk & 1][nj][0], bfr[kk & 1][nj][1]);
        }
        __syncthreads();
    }

    #pragma unroll
    for (int mi = 0; mi < 2; mi++) {
        size_t r = row0 + wm * 32 + mi * 16 + (lane >> 2);
        #pragma unroll
        for (int nj = 0; nj < 8; nj++) {
            size_t c = col0 + wn * 64 + nj * 8 + 2 * (lane & 3);
            if (EPI == 1) {
                float* C = (float*)Cv;
                const float2 r0 = *(const float2*)(R + r * (size_t)N + c);
                const float2 r1 = *(const float2*)(R + (r + 8) * (size_t)N + c);
                float2 v0 = make_float2(acc[mi][nj][0] + r0.x, acc[mi][nj][1] + r0.y);
                float2 v1 = make_float2(acc[mi][nj][2] + r1.x, acc[mi][nj][3] + r1.y);
                *(float2*)(C + r * (size_t)N + c) = v0;
                *(float2*)(C + (r + 8) * (size_t)N + c) = v1;
            } else {
                __half2* C = (__half2*)Cv;
                C[(r * (size_t)N + c) >> 1]       = __floats2half2_rn(acc[mi][nj][0], acc[mi][nj][1]);
                C[((r + 8) * (size_t)N + c) >> 1] = __floats2half2_rn(acc[mi][nj][2], acc[mi][nj][3]);
            }
        }
    }
}

// ---------------- fused gate/up GEMM: act(half) = rn(silu(A@Wg^T) * (A@Wu^T)) ----------------
__global__ __launch_bounds__(NTHREADS, 1) void gemm_gateup_mma(
    const __half* __restrict__ A, const __half* __restrict__ Wg,
    const __half* __restrict__ Wu, __half* __restrict__ C, int K, int N)
{
    extern __shared__ __align__(1024) char smem[];
    uint32_t sb = s2u(smem);
    int tid = threadIdx.x;
    int lane = tid & 31, w = tid >> 5;
    int wm = w >> 2;      // 0..3 (32-row slice)
    int wn = w & 3;       // 0..3 (32-col slice)
    size_t row0 = (size_t)blockIdx.x * 128;
    size_t col0 = (size_t)blockIdx.y * 128;
    const int NK = K / BK;

    const __half* Abase = A + row0 * (size_t)K;
    const __half* Gbase = Wg + col0 * (size_t)K;
    const __half* Ubase = Wu + col0 * (size_t)K;
    int nvalid = (int)((size_t)N - col0 < 128 ? (size_t)N - col0 : 128);

    auto load_stage = [&](int slot, int j) {
        uint32_t ab = sb + (uint32_t)slot * STAGE_B;
        uint32_t gb = ab + 16384;
        uint32_t ub = gb + 16384;
        int kt = j * BK;
        #pragma unroll
        for (int p = 0; p < 2; p++) {
            int idx = p * NTHREADS + tid;
            int r = idx >> 3, c = idx & 7;
            cpa16(ab + sw128((r << 7) + (c << 4)),
                  (const char*)(Abase + (size_t)r * K + kt) + (c << 4));
        }
        #pragma unroll
        for (int p = 0; p < 2; p++) {
            int idx = p * NTHREADS + tid;
            int r = idx >> 3, c = idx & 7;
            if (r < nvalid) {
                uint32_t swo = sw128((r << 7) + (c << 4));
                cpa16(gb + swo, (const char*)(Gbase + (size_t)r * K + kt) + (c << 4));
                cpa16(ub + swo, (const char*)(Ubase + (size_t)r * K + kt) + (c << 4));
            }
        }
    };

    auto load_afr = [&](uint32_t ab, int kk, uint32_t af[2][4]) {
        #pragma unroll
        for (int mi = 0; mi < 2; mi++) {
            uint32_t off = (uint32_t)((wm * 32 + mi * 16 + (lane & 15)) << 7)
                         + (uint32_t)((kk << 5) + ((lane >> 4) << 4));
            ldsm4(af[mi][0], af[mi][1], af[mi][2], af[mi][3], ab + sw128(off));
        }
    };
    auto load_wfr = [&](uint32_t wb, int kk, uint32_t wf[4][2]) {
        #pragma unroll
        for (int bi = 0; bi < 2; bi++) {
            uint32_t off = (uint32_t)((wn * 32 + bi * 16 + ((lane >> 4) << 3) + (lane & 7)) << 7)
                         + (uint32_t)((kk << 5) + (((lane >> 3) & 1) << 4));
            ldsm4(wf[2*bi][0], wf[2*bi][1], wf[2*bi+1][0], wf[2*bi+1][1], wb + sw128(off));
        }
    };

    float accg[2][4][4], accu[2][4][4];
    #pragma unroll
    for (int i = 0; i < 2; i++)
        #pragma unroll
        for (int jx = 0; jx < 4; jx++)
            #pragma unroll
            for (int e = 0; e < 4; e++) { accg[i][jx][e] = 0.f; accu[i][jx][e] = 0.f; }

    #pragma unroll
    for (int p = 0; p < STAGES - 1; p++) {
        load_stage(p, p);
        asm volatile("cp.async.commit_group;");
    }

    for (int j = 0; j < NK; j++) {
        asm volatile("cp.async.wait_group %0;" :: "n"(STAGES - 2));
        __syncthreads();
        if (j + STAGES - 1 < NK) load_stage((j + STAGES - 1) & 3, j + STAGES - 1);
        asm volatile("cp.async.commit_group;");

        int slot = j & 3;
        uint32_t ab = sb + (uint32_t)slot * STAGE_B;
        uint32_t gb = ab + 16384;
        uint32_t ub = gb + 16384;

        uint32_t afr[2][2][4], gfr[2][4][2], ufr[2][4][2];
        load_afr(ab, 0, afr[0]);
        load_wfr(gb, 0, gfr[0]);
        load_wfr(ub, 0, ufr[0]);
        #pragma unroll
        for (int kk = 0; kk < 4; kk++) {
            if (kk < 3) {
                load_afr(ab, kk + 1, afr[(kk + 1) & 1]);
                load_wfr(gb, kk + 1, gfr[(kk + 1) & 1]);
                load_wfr(ub, kk + 1, ufr[(kk + 1) & 1]);
            }
            #pragma unroll
            for (int mi = 0; mi < 2; mi++)
                #pragma unroll
                for (int nj = 0; nj < 4; nj++) {
                    mma_f16(accg[mi][nj], afr[kk & 1][mi], gfr[kk & 1][nj][0], gfr[kk & 1][nj][1]);
                    mma_f16(accu[mi][nj], afr[kk & 1][mi], ufr[kk & 1][nj][0], ufr[kk & 1][nj][1]);
                }
        }
        __syncthreads();
    }

    #pragma unroll
    for (int mi = 0; mi < 2; mi++) {
        size_t r = row0 + wm * 32 + mi * 16 + (lane >> 2);
        #pragma unroll
        for (int nj = 0; nj < 4; nj++) {
            size_t c = col0 + wn * 32 + nj * 8 + 2 * (lane & 3);
            if (c < (size_t)N) {
                float gx = accg[mi][nj][0], ux = accu[mi][nj][0];
                float gy = accg[mi][nj][1], uy = accu[mi][nj][1];
                float gz = accg[mi][nj][2], uz = accu[mi][nj][2];
                float gw = accg[mi][nj][3], uw = accu[mi][nj][3];
                __half2 v0 = __floats2half2_rn(gx / (1.f + expf(-gx)) * ux,
                                               gy / (1.f + expf(-gy)) * uy);
                __half2 v1 = __floats2half2_rn(gz / (1.f + expf(-gz)) * uz,
                                               gw / (1.f + expf(-gw)) * uw);
                *(__half2*)(C + r * (size_t)N + c) = v0;
                *(__half2*)(C + (r + 8) * (size_t)N + c) = v1;
            }
        }
    }
}

// ---------------- launch ----------------
extern "C" void kernel_launch(void* const* d_in, const int* in_sizes, int n_in,
                              void* d_out, int out_size)
{
    const float* x      = (const float*)d_in[0];
    const float* in_w   = (const float*)d_in[2];
    const float* post_w = (const float*)d_in[3];
    const float* Wq     = (const float*)d_in[4];
    const float* Wo     = (const float*)d_in[5];
    const float* Wg     = (const float*)d_in[6];
    const float* Wu     = (const float*)d_in[7];
    const float* Wd     = (const float*)d_in[8];
    float* out = (float*)d_out;

    __half *hnorm, *hpost, *act, *hWqT, *hWo, *hWqo, *hWg, *hWu, *hWd;
    float *hidden;
    cudaGetSymbolAddress((void**)&hnorm,  g_hnorm);
    cudaGetSymbolAddress((void**)&hidden, g_hidden);
    cudaGetSymbolAddress((void**)&hpost,  g_hpost);
    cudaGetSymbolAddress((void**)&act,    g_act);
    cudaGetSymbolAddress((void**)&hWqT,   g_hWqT);
    cudaGetSymbolAddress((void**)&hWo,    g_hWo);
    cudaGetSymbolAddress((void**)&hWqo,   g_hWqo);
    cudaGetSymbolAddress((void**)&hWg,    g_hWg);
    cudaGetSymbolAddress((void**)&hWu,    g_hWu);
    cudaGetSymbolAddress((void**)&hWd,    g_hWd);

    static bool attr_done = false;
    if (!attr_done) {
        cudaFuncSetAttribute(gemm_mma<0>, cudaFuncAttributeMaxDynamicSharedMemorySize, SMEM_TOTAL);
        cudaFuncSetAttribute(gemm_mma<1>, cudaFuncAttributeMaxDynamicSharedMemorySize, SMEM_TOTAL);
        cudaFuncSetAttribute(gemm_gateup_mma, cudaFuncAttributeMaxDynamicSharedMemorySize, SMEM_TOTAL);
        attr_done = true;
    }

    const int CB = 1184;
    // weights -> fp16 scratch; Wq additionally transposed (for the Wqo fold)
    to_f16_kernel<<<CB, 256>>>((const float4*)Wo, (uint2*)hWo, (long)HID * HID / 4);
    transpose_f16_kernel<<<dim3(HID/32, HID/32), dim3(32, 8)>>>(Wq, hWqT);
    // Wqo = rn16(Wo @ Wq):  C[i,j] = sum_q Wo[i,q] * WqT[j,q]
    gemm_mma<0><<<dim3(HID/128, HID/256), NTHREADS, SMEM_TOTAL>>>(hWo, hWqT, nullptr, hWqo, HID, HID);
    to_f16_kernel<<<CB, 256>>>((const float4*)Wg, (uint2*)hWg, (long)INTERD * HID / 4);
    to_f16_kernel<<<CB, 256>>>((const float4*)Wu, (uint2*)hWu, (long)INTERD * HID / 4);
    to_f16_kernel<<<CB, 256>>>((const float4*)Wd, (uint2*)hWd, (long)HID * INTERD / 4);

    // 1. h_norm = rn(rmsnorm(x) * in_w)
    rmsnorm_kernel<<<T_TOK, 256>>>(x, in_w, hnorm);
    // 2+3 fused. hidden = x + h_norm @ Wqo^T
    gemm_mma<1><<<dim3(T_TOK/128, HID/256), NTHREADS, SMEM_TOTAL>>>(hnorm, hWqo, x, hidden, HID, HID);
    // 4. h_post = rn(rmsnorm(hidden) * post_w)
    rmsnorm_kernel<<<T_TOK, 256>>>(hidden, post_w, hpost);
    // 5. act = rn(silu(h_post @ Wg^T) * (h_post @ Wu^T))   [86 tiles, last ragged 64]
    gemm_gateup_mma<<<dim3(T_TOK/128, (INTERD + 127)/128), NTHREADS, SMEM_TOTAL>>>(hpost, hWg, hWu, act, HID, INTERD);
    // 6. out = hidden + act @ Wd^T
    gemm_mma<1><<<dim3(T_TOK/128, HID/256), NTHREADS, SMEM_TOTAL>>>(act, hWd, hidden, out, INTERD, HID);
}

// round 10
// speedup vs baseline: 8.5487x; 1.0122x over previous
#include <cuda_runtime.h>
#include <cuda_fp16.h>
#include <cstdint>
#include <math.h>

#define T_TOK  4096
#define HID    2048
#define INTERD 10944
#define EPS    1e-6f

#define BK 64            // 64 halves = 128 bytes per row
#define STAGES 4
#define STAGE_B  49152
#define SMEM_TOTAL (STAGES * STAGE_B)  // 196608

#define NTHREADS 512

// ---------------- scratch (device globals; allocation-free rule) ----------------
__device__ __half g_hnorm [(size_t)T_TOK * HID];
__device__ float  g_hidden[(size_t)T_TOK * HID];
__device__ __half g_hpost [(size_t)T_TOK * HID];
__device__ __half g_act   [(size_t)T_TOK * INTERD];
__device__ __half g_hWqT  [(size_t)HID * HID];   // fp16(Wq)^T  [h_in, q]
__device__ __half g_hWo   [(size_t)HID * HID];
__device__ __half g_hWqo  [(size_t)HID * HID];   // fp16(Wo @ Wq) [h_out, h_in]
__device__ __half g_hWg   [(size_t)INTERD * HID];
__device__ __half g_hWu   [(size_t)INTERD * HID];
__device__ __half g_hWd   [(size_t)HID * INTERD];

// ---------------- PTX helpers ----------------
static __device__ __forceinline__ uint32_t s2u(const void* p) {
    uint32_t a;
    asm("{ .reg .u64 t; cvta.to.shared.u64 t, %1; cvt.u32.u64 %0, t; }" : "=r"(a) : "l"(p));
    return a;
}
static __device__ __forceinline__ void cpa16(uint32_t s, const void* g) {
    asm volatile("cp.async.cg.shared.global [%0], [%1], 16;" :: "r"(s), "l"(g));
}
static __device__ __forceinline__ void ldsm4(uint32_t& r0, uint32_t& r1,
                                             uint32_t& r2, uint32_t& r3, uint32_t addr) {
    asm volatile("ldmatrix.sync.aligned.m8n8.x4.shared.b16 {%0,%1,%2,%3}, [%4];"
                 : "=r"(r0), "=r"(r1), "=r"(r2), "=r"(r3) : "r"(addr));
}
static __device__ __forceinline__ void mma_f16(float* c, const uint32_t* a,
                                               uint32_t b0, uint32_t b1) {
    asm volatile(
        "mma.sync.aligned.m16n8k16.row.col.f32.f16.f16.f32 "
        "{%0,%1,%2,%3}, {%4,%5,%6,%7}, {%8,%9}, {%0,%1,%2,%3};"
        : "+f"(c[0]), "+f"(c[1]), "+f"(c[2]), "+f"(c[3])
        : "r"(a[0]), "r"(a[1]), "r"(a[2]), "r"(a[3]), "r"(b0), "r"(b1));
}
static __device__ __forceinline__ uint32_t sw128(uint32_t off) {
    return off ^ ((off >> 3) & 0x70);
}
// fast silu via explicit intrinsics: 1 EX2 + 1 RCP, no refinement chain
static __device__ __forceinline__ float fsilu(float g) {
    return __fdividef(g, 1.f + __expf(-g));
}

// ---------------- RMSNorm (fp32 in, fp16-RNE out) ----------------
__global__ __launch_bounds__(256) void rmsnorm_kernel(
    const float* __restrict__ x, const float* __restrict__ w, __half* __restrict__ out)
{
    long row = blockIdx.x;
    const float4* xr = (const float4*)(x + row * (long)HID);
    const float4* wr = (const float4*)w;
    __half2* orow = (__half2*)(out + row * (long)HID);
    int tid = threadIdx.x;

    float4 v0 = xr[tid];
    float4 v1 = xr[tid + 256];
    float ss = v0.x*v0.x + v0.y*v0.y + v0.z*v0.z + v0.w*v0.w
             + v1.x*v1.x + v1.y*v1.y + v1.z*v1.z + v1.w*v1.w;

    #pragma unroll
    for (int off = 16; off > 0; off >>= 1)
        ss += __shfl_xor_sync(0xffffffffu, ss, off);

    __shared__ float warp_ss[8];
    __shared__ float s_scale;
    int lane = tid & 31, wid = tid >> 5;
    if (lane == 0) warp_ss[wid] = ss;
    __syncthreads();
    if (tid == 0) {
        float tot = 0.f;
        #pragma unroll
        for (int i = 0; i < 8; i++) tot += warp_ss[i];
        s_scale = rsqrtf(tot / (float)HID + EPS);
    }
    __syncthreads();
    float scale = s_scale;

    float4 w0 = wr[tid];
    float4 w1 = wr[tid + 256];
    orow[2*tid]       = __floats2half2_rn(v0.x * scale * w0.x, v0.y * scale * w0.y);
    orow[2*tid + 1]   = __floats2half2_rn(v0.z * scale * w0.z, v0.w * scale * w0.w);
    orow[2*tid + 512] = __floats2half2_rn(v1.x * scale * w1.x, v1.y * scale * w1.y);
    orow[2*tid + 513] = __floats2half2_rn(v1.z * scale * w1.z, v1.w * scale * w1.w);
}

// ---------------- fp32 -> fp16(RNE) elementwise ----------------
__global__ __launch_bounds__(256) void to_f16_kernel(
    const float4* __restrict__ s, uint2* __restrict__ d, long n4)
{
    long i = (long)blockIdx.x * blockDim.x + threadIdx.x;
    long stride = (long)gridDim.x * blockDim.x;
    for (; i < n4; i += stride) {
        float4 v = s[i];
        __half2 lo = __floats2half2_rn(v.x, v.y);
        __half2 hi = __floats2half2_rn(v.z, v.w);
        uint2 o;
        o.x = *(uint32_t*)&lo;
        o.y = *(uint32_t*)&hi;
        d[i] = o;
    }
}

// ---------------- fp32 [2048x2048] -> transposed fp16 ----------------
__global__ __launch_bounds__(256) void transpose_f16_kernel(
    const float* __restrict__ src, __half* __restrict__ dst)
{
    __shared__ float tile[32][33];
    int x = blockIdx.x * 32 + threadIdx.x;   // src col
    int y0 = blockIdx.y * 32 + threadIdx.y;  // src row
    #pragma unroll
    for (int i = 0; i < 32; i += 8)
        tile[threadIdx.y + i][threadIdx.x] = src[(size_t)(y0 + i) * HID + x];
    __syncthreads();
    int tx = blockIdx.y * 32 + threadIdx.x;  // dst col (= src row)
    int ty = blockIdx.x * 32 + threadIdx.y;  // dst row (= src col)
    #pragma unroll
    for (int i = 0; i < 32; i += 8)
        dst[(size_t)(ty + i) * HID + tx] = __float2half_rn(tile[threadIdx.x][threadIdx.y + i]);
}

// ---------------- plain GEMM: C[M,N] = A @ W^T (+R), mma.sync fp16 ----------------
// CTA tile 128x256, BK=64, 4-slot/3-inflight cp.async, single sync per iter,
// 16 warps (4M x 4N), warp tile 32x64, kk-level fragment double buffering.
// EPI 0: C(half) = rn(A@W^T);  EPI 1: C(float) = R + A@W^T
template<int EPI>
__global__ __launch_bounds__(NTHREADS, 1) void gemm_mma(
    const __half* __restrict__ A, const __half* __restrict__ W,
    const float* __restrict__ R, void* __restrict__ Cv, int K, int N)
{
    extern __shared__ __align__(1024) char smem[];
    uint32_t sb = s2u(smem);
    int tid = threadIdx.x;
    int lane = tid & 31, w = tid >> 5;
    int wm = w >> 2;      // 0..3  (32-row slice)
    int wn = w & 3;       // 0..3  (64-col slice)
    size_t row0 = (size_t)blockIdx.x * 128;
    size_t col0 = (size_t)blockIdx.y * 256;
    const int NK = K / BK;

    const __half* Abase = A + row0 * (size_t)K;
    const __half* Wbase = W + col0 * (size_t)K;

    auto load_stage = [&](int slot, int j) {
        uint32_t ab = sb + (uint32_t)slot * STAGE_B;
        uint32_t bb = ab + 16384;
        int kt = j * BK;
        #pragma unroll
        for (int p = 0; p < 2; p++) {
            int idx = p * NTHREADS + tid;
            int r = idx >> 3, c = idx & 7;   // 8 x 16B chunks per 128B row
            cpa16(ab + sw128((r << 7) + (c << 4)),
                  (const char*)(Abase + (size_t)r * K + kt) + (c << 4));
        }
        #pragma unroll
        for (int p = 0; p < 4; p++) {
            int idx = p * NTHREADS + tid;
            int r = idx >> 3, c = idx & 7;
            cpa16(bb + sw128((r << 7) + (c << 4)),
                  (const char*)(Wbase + (size_t)r * K + kt) + (c << 4));
        }
    };

    auto load_afr = [&](uint32_t ab, int kk, uint32_t af[2][4]) {
        #pragma unroll
        for (int mi = 0; mi < 2; mi++) {
            uint32_t off = (uint32_t)((wm * 32 + mi * 16 + (lane & 15)) << 7)
                         + (uint32_t)((kk << 5) + ((lane >> 4) << 4));
            ldsm4(af[mi][0], af[mi][1], af[mi][2], af[mi][3], ab + sw128(off));
        }
    };
    auto load_bfr = [&](uint32_t bb, int kk, uint32_t bf[8][2]) {
        #pragma unroll
        for (int bi = 0; bi < 4; bi++) {
            uint32_t off = (uint32_t)((wn * 64 + bi * 16 + ((lane >> 4) << 3) + (lane & 7)) << 7)
                         + (uint32_t)((kk << 5) + (((lane >> 3) & 1) << 4));
            ldsm4(bf[2*bi][0], bf[2*bi][1], bf[2*bi+1][0], bf[2*bi+1][1], bb + sw128(off));
        }
    };

    float acc[2][8][4];
    #pragma unroll
    for (int i = 0; i < 2; i++)
        #pragma unroll
        for (int jx = 0; jx < 8; jx++)
            #pragma unroll
            for (int e = 0; e < 4; e++) acc[i][jx][e] = 0.f;

    #pragma unroll
    for (int p = 0; p < STAGES - 1; p++) {
        load_stage(p, p);
        asm volatile("cp.async.commit_group;");
    }

    for (int j = 0; j < NK; j++) {
        asm volatile("cp.async.wait_group %0;" :: "n"(STAGES - 2));
        __syncthreads();
        if (j + STAGES - 1 < NK) load_stage((j + STAGES - 1) & 3, j + STAGES - 1);
        asm volatile("cp.async.commit_group;");

        int slot = j & 3;
        uint32_t ab = sb + (uint32_t)slot * STAGE_B;
        uint32_t bb = ab + 16384;

        uint32_t afr[2][2][4], bfr[2][8][2];
        load_afr(ab, 0, afr[0]);
        load_bfr(bb, 0, bfr[0]);
        #pragma unroll
        for (int kk = 0; kk < 4; kk++) {
            if (kk < 3) {
                load_afr(ab, kk + 1, afr[(kk + 1) & 1]);
                load_bfr(bb, kk + 1, bfr[(kk + 1) & 1]);
            }
            #pragma unroll
            for (int mi = 0; mi < 2; mi++)
                #pragma unroll
                for (int nj = 0; nj < 8; nj++)
                    mma_f16(acc[mi][nj], afr[kk & 1][mi], bfr[kk & 1][nj][0], bfr[kk & 1][nj][1]);
        }
        __syncthreads();
    }

    #pragma unroll
    for (int mi = 0; mi < 2; mi++) {
        size_t r = row0 + wm * 32 + mi * 16 + (lane >> 2);
        #pragma unroll
        for (int nj = 0; nj < 8; nj++) {
            size_t c = col0 + wn * 64 + nj * 8 + 2 * (lane & 3);
            if (EPI == 1) {
                float* C = (float*)Cv;
                const float2 r0 = *(const float2*)(R + r * (size_t)N + c);
                const float2 r1 = *(const float2*)(R + (r + 8) * (size_t)N + c);
                float2 v0 = make_float2(acc[mi][nj][0] + r0.x, acc[mi][nj][1] + r0.y);
                float2 v1 = make_float2(acc[mi][nj][2] + r1.x, acc[mi][nj][3] + r1.y);
                *(float2*)(C + r * (size_t)N + c) = v0;
                *(float2*)(C + (r + 8) * (size_t)N + c) = v1;
            } else {
                __half2* C = (__half2*)Cv;
                C[(r * (size_t)N + c) >> 1]       = __floats2half2_rn(acc[mi][nj][0], acc[mi][nj][1]);
                C[((r + 8) * (size_t)N + c) >> 1] = __floats2half2_rn(acc[mi][nj][2], acc[mi][nj][3]);
            }
        }
    }
}

// ---------------- fused gate/up GEMM: act(half) = rn(silu(A@Wg^T) * (A@Wu^T)) ----------------
__global__ __launch_bounds__(NTHREADS, 1) void gemm_gateup_mma(
    const __half* __restrict__ A, const __half* __restrict__ Wg,
    const __half* __restrict__ Wu, __half* __restrict__ C, int K, int N)
{
    extern __shared__ __align__(1024) char smem[];
    uint32_t sb = s2u(smem);
    int tid = threadIdx.x;
    int lane = tid & 31, w = tid >> 5;
    int wm = w >> 2;      // 0..3 (32-row slice)
    int wn = w & 3;       // 0..3 (32-col slice)
    size_t row0 = (size_t)blockIdx.x * 128;
    size_t col0 = (size_t)blockIdx.y * 128;
    const int NK = K / BK;

    const __half* Abase = A + row0 * (size_t)K;
    const __half* Gbase = Wg + col0 * (size_t)K;
    const __half* Ubase = Wu + col0 * (size_t)K;
    int nvalid = (int)((size_t)N - col0 < 128 ? (size_t)N - col0 : 128);

    auto load_stage = [&](int slot, int j) {
        uint32_t ab = sb + (uint32_t)slot * STAGE_B;
        uint32_t gb = ab + 16384;
        uint32_t ub = gb + 16384;
        int kt = j * BK;
        #pragma unroll
        for (int p = 0; p < 2; p++) {
            int idx = p * NTHREADS + tid;
            int r = idx >> 3, c = idx & 7;
            cpa16(ab + sw128((r << 7) + (c << 4)),
                  (const char*)(Abase + (size_t)r * K + kt) + (c << 4));
        }
        #pragma unroll
        for (int p = 0; p < 2; p++) {
            int idx = p * NTHREADS + tid;
            int r = idx >> 3, c = idx & 7;
            if (r < nvalid) {
                uint32_t swo = sw128((r << 7) + (c << 4));
                cpa16(gb + swo, (const char*)(Gbase + (size_t)r * K + kt) + (c << 4));
                cpa16(ub + swo, (const char*)(Ubase + (size_t)r * K + kt) + (c << 4));
            }
        }
    };

    auto load_afr = [&](uint32_t ab, int kk, uint32_t af[2][4]) {
        #pragma unroll
        for (int mi = 0; mi < 2; mi++) {
            uint32_t off = (uint32_t)((wm * 32 + mi * 16 + (lane & 15)) << 7)
                         + (uint32_t)((kk << 5) + ((lane >> 4) << 4));
            ldsm4(af[mi][0], af[mi][1], af[mi][2], af[mi][3], ab + sw128(off));
        }
    };
    auto load_wfr = [&](uint32_t wb, int kk, uint32_t wf[4][2]) {
        #pragma unroll
        for (int bi = 0; bi < 2; bi++) {
            uint32_t off = (uint32_t)((wn * 32 + bi * 16 + ((lane >> 4) << 3) + (lane & 7)) << 7)
                         + (uint32_t)((kk << 5) + (((lane >> 3) & 1) << 4));
            ldsm4(wf[2*bi][0], wf[2*bi][1], wf[2*bi+1][0], wf[2*bi+1][1], wb + sw128(off));
        }
    };

    float accg[2][4][4], accu[2][4][4];
    #pragma unroll
    for (int i = 0; i < 2; i++)
        #pragma unroll
        for (int jx = 0; jx < 4; jx++)
            #pragma unroll
            for (int e = 0; e < 4; e++) { accg[i][jx][e] = 0.f; accu[i][jx][e] = 0.f; }

    #pragma unroll
    for (int p = 0; p < STAGES - 1; p++) {
        load_stage(p, p);
        asm volatile("cp.async.commit_group;");
    }

    for (int j = 0; j < NK; j++) {
        asm volatile("cp.async.wait_group %0;" :: "n"(STAGES - 2));
        __syncthreads();
        if (j + STAGES - 1 < NK) load_stage((j + STAGES - 1) & 3, j + STAGES - 1);
        asm volatile("cp.async.commit_group;");

        int slot = j & 3;
        uint32_t ab = sb + (uint32_t)slot * STAGE_B;
        uint32_t gb = ab + 16384;
        uint32_t ub = gb + 16384;

        uint32_t afr[2][2][4], gfr[2][4][2], ufr[2][4][2];
        load_afr(ab, 0, afr[0]);
        load_wfr(gb, 0, gfr[0]);
        load_wfr(ub, 0, ufr[0]);
        #pragma unroll
        for (int kk = 0; kk < 4; kk++) {
            if (kk < 3) {
                load_afr(ab, kk + 1, afr[(kk + 1) & 1]);
                load_wfr(gb, kk + 1, gfr[(kk + 1) & 1]);
                load_wfr(ub, kk + 1, ufr[(kk + 1) & 1]);
            }
            #pragma unroll
            for (int mi = 0; mi < 2; mi++)
                #pragma unroll
                for (int nj = 0; nj < 4; nj++) {
                    mma_f16(accg[mi][nj], afr[kk & 1][mi], gfr[kk & 1][nj][0], gfr[kk & 1][nj][1]);
                    mma_f16(accu[mi][nj], afr[kk & 1][mi], ufr[kk & 1][nj][0], ufr[kk & 1][nj][1]);
                }
        }
        __syncthreads();
    }

    #pragma unroll
    for (int mi = 0; mi < 2; mi++) {
        size_t r = row0 + wm * 32 + mi * 16 + (lane >> 2);
        #pragma unroll
        for (int nj = 0; nj < 4; nj++) {
            size_t c = col0 + wn * 32 + nj * 8 + 2 * (lane & 3);
            if (c < (size_t)N) {
                __half2 v0 = __floats2half2_rn(fsilu(accg[mi][nj][0]) * accu[mi][nj][0],
                                               fsilu(accg[mi][nj][1]) * accu[mi][nj][1]);
                __half2 v1 = __floats2half2_rn(fsilu(accg[mi][nj][2]) * accu[mi][nj][2],
                                               fsilu(accg[mi][nj][3]) * accu[mi][nj][3]);
                *(__half2*)(C + r * (size_t)N + c) = v0;
                *(__half2*)(C + (r + 8) * (size_t)N + c) = v1;
            }
        }
    }
}

// ---------------- launch ----------------
extern "C" void kernel_launch(void* const* d_in, const int* in_sizes, int n_in,
                              void* d_out, int out_size)
{
    const float* x      = (const float*)d_in[0];
    const float* in_w   = (const float*)d_in[2];
    const float* post_w = (const float*)d_in[3];
    const float* Wq     = (const float*)d_in[4];
    const float* Wo     = (const float*)d_in[5];
    const float* Wg     = (const float*)d_in[6];
    const float* Wu     = (const float*)d_in[7];
    const float* Wd     = (const float*)d_in[8];
    float* out = (float*)d_out;

    __half *hnorm, *hpost, *act, *hWqT, *hWo, *hWqo, *hWg, *hWu, *hWd;
    float *hidden;
    cudaGetSymbolAddress((void**)&hnorm,  g_hnorm);
    cudaGetSymbolAddress((void**)&hidden, g_hidden);
    cudaGetSymbolAddress((void**)&hpost,  g_hpost);
    cudaGetSymbolAddress((void**)&act,    g_act);
    cudaGetSymbolAddress((void**)&hWqT,   g_hWqT);
    cudaGetSymbolAddress((void**)&hWo,    g_hWo);
    cudaGetSymbolAddress((void**)&hWqo,   g_hWqo);
    cudaGetSymbolAddress((void**)&hWg,    g_hWg);
    cudaGetSymbolAddress((void**)&hWu,    g_hWu);
    cudaGetSymbolAddress((void**)&hWd,    g_hWd);

    static cudaStream_t s2 = nullptr;
    static cudaEvent_t ev_fork = nullptr, ev_join = nullptr;
    if (s2 == nullptr) {
        cudaStreamCreateWithFlags(&s2, cudaStreamNonBlocking);
        cudaEventCreateWithFlags(&ev_fork, cudaEventDisableTiming);
        cudaEventCreateWithFlags(&ev_join, cudaEventDisableTiming);
        cudaFuncSetAttribute(gemm_mma<0>, cudaFuncAttributeMaxDynamicSharedMemorySize, SMEM_TOTAL);
        cudaFuncSetAttribute(gemm_mma<1>, cudaFuncAttributeMaxDynamicSharedMemorySize, SMEM_TOTAL);
        cudaFuncSetAttribute(gemm_gateup_mma, cudaFuncAttributeMaxDynamicSharedMemorySize, SMEM_TOTAL);
    }

    const int CB = 1184;

    // ---- fork: big weight converts on s2, overlapped with the attention chain ----
    cudaEventRecord(ev_fork, 0);
    cudaStreamWaitEvent(s2, ev_fork, 0);
    to_f16_kernel<<<CB, 256, 0, s2>>>((const float4*)Wg, (uint2*)hWg, (long)INTERD * HID / 4);
    to_f16_kernel<<<CB, 256, 0, s2>>>((const float4*)Wu, (uint2*)hWu, (long)INTERD * HID / 4);
    to_f16_kernel<<<CB, 256, 0, s2>>>((const float4*)Wd, (uint2*)hWd, (long)HID * INTERD / 4);
    cudaEventRecord(ev_join, s2);

    // ---- main stream: Wqo fold + attention + rmsnorms ----
    to_f16_kernel<<<CB, 256>>>((const float4*)Wo, (uint2*)hWo, (long)HID * HID / 4);
    transpose_f16_kernel<<<dim3(HID/32, HID/32), dim3(32, 8)>>>(Wq, hWqT);
    // 1. h_norm = rn(rmsnorm(x) * in_w)
    rmsnorm_kernel<<<T_TOK, 256>>>(x, in_w, hnorm);
    // Wqo = rn16(Wo @ Wq):  C[i,j] = sum_q Wo[i,q] * WqT[j,q]
    gemm_mma<0><<<dim3(HID/128, HID/256), NTHREADS, SMEM_TOTAL>>>(hWo, hWqT, nullptr, hWqo, HID, HID);
    // 2+3 fused. hidden = x + h_norm @ Wqo^T
    gemm_mma<1><<<dim3(T_TOK/128, HID/256), NTHREADS, SMEM_TOTAL>>>(hnorm, hWqo, x, hidden, HID, HID);
    // 4. h_post = rn(rmsnorm(hidden) * post_w)
    rmsnorm_kernel<<<T_TOK, 256>>>(hidden, post_w, hpost);

    // ---- join: converts must be done before the MLP GEMMs ----
    cudaStreamWaitEvent(0, ev_join, 0);

    // 5. act = rn(silu(h_post @ Wg^T) * (h_post @ Wu^T))   [86 tiles, last ragged 64]
    gemm_gateup_mma<<<dim3(T_TOK/128, (INTERD + 127)/128), NTHREADS, SMEM_TOTAL>>>(hpost, hWg, hWu, act, HID, INTERD);
    // 6. out = hidden + act @ Wd^T
    gemm_mma<1><<<dim3(T_TOK/128, HID/256), NTHREADS, SMEM_TOTAL>>>(act, hWd, hidden, out, INTERD, HID);
}

// round 11
// speedup vs baseline: 8.7128x; 1.0192x over previous
#include <cuda_runtime.h>
#include <cuda_fp16.h>
#include <cstdint>
#include <math.h>

#define T_TOK  4096
#define HID    2048
#define INTERD 10944
#define EPS    1e-6f

#define BK 64            // 64 halves = 128 bytes per row
#define STAGES 4
#define STAGE_B  49152
#define SMEM_TOTAL (STAGES * STAGE_B)  // 196608

#define NTHREADS 512

// ---------------- scratch (device globals; allocation-free rule) ----------------
__device__ __half g_hnorm [(size_t)T_TOK * HID];
__device__ float  g_hidden[(size_t)T_TOK * HID];
__device__ __half g_hpost [(size_t)T_TOK * HID];
__device__ __half g_act   [(size_t)T_TOK * INTERD];
__device__ __half g_hWqT  [(size_t)HID * HID];   // fp16(Wq)^T  [h_in, q]
__device__ __half g_hWo   [(size_t)HID * HID];
__device__ __half g_hWqo  [(size_t)HID * HID];   // fp16(Wo @ Wq) [h_out, h_in]
__device__ __half g_hWg   [(size_t)INTERD * HID];
__device__ __half g_hWu   [(size_t)INTERD * HID];
__device__ __half g_hWd   [(size_t)HID * INTERD];

// ---------------- PTX helpers ----------------
static __device__ __forceinline__ uint32_t s2u(const void* p) {
    uint32_t a;
    asm("{ .reg .u64 t; cvta.to.shared.u64 t, %1; cvt.u32.u64 %0, t; }" : "=r"(a) : "l"(p));
    return a;
}
static __device__ __forceinline__ void cpa16(uint32_t s, const void* g) {
    asm volatile("cp.async.cg.shared.global [%0], [%1], 16;" :: "r"(s), "l"(g));
}
static __device__ __forceinline__ void ldsm4(uint32_t& r0, uint32_t& r1,
                                             uint32_t& r2, uint32_t& r3, uint32_t addr) {
    asm volatile("ldmatrix.sync.aligned.m8n8.x4.shared.b16 {%0,%1,%2,%3}, [%4];"
                 : "=r"(r0), "=r"(r1), "=r"(r2), "=r"(r3) : "r"(addr));
}
static __device__ __forceinline__ void mma_f16(float* c, const uint32_t* a,
                                               uint32_t b0, uint32_t b1) {
    asm volatile(
        "mma.sync.aligned.m16n8k16.row.col.f32.f16.f16.f32 "
        "{%0,%1,%2,%3}, {%4,%5,%6,%7}, {%8,%9}, {%0,%1,%2,%3};"
        : "+f"(c[0]), "+f"(c[1]), "+f"(c[2]), "+f"(c[3])
        : "r"(a[0]), "r"(a[1]), "r"(a[2]), "r"(a[3]), "r"(b0), "r"(b1));
}
static __device__ __forceinline__ uint32_t sw128(uint32_t off) {
    return off ^ ((off >> 3) & 0x70);
}
// fast silu via explicit intrinsics: 1 EX2 + 1 RCP
static __device__ __forceinline__ float fsilu(float g) {
    return __fdividef(g, 1.f + __expf(-g));
}

// ---------------- RMSNorm (fp32 in, fp16-RNE out) ----------------
__global__ __launch_bounds__(256) void rmsnorm_kernel(
    const float* __restrict__ x, const float* __restrict__ w, __half* __restrict__ out)
{
    long row = blockIdx.x;
    const float4* xr = (const float4*)(x + row * (long)HID);
    const float4* wr = (const float4*)w;
    __half2* orow = (__half2*)(out + row * (long)HID);
    int tid = threadIdx.x;

    float4 v0 = xr[tid];
    float4 v1 = xr[tid + 256];
    float ss = v0.x*v0.x + v0.y*v0.y + v0.z*v0.z + v0.w*v0.w
             + v1.x*v1.x + v1.y*v1.y + v1.z*v1.z + v1.w*v1.w;

    #pragma unroll
    for (int off = 16; off > 0; off >>= 1)
        ss += __shfl_xor_sync(0xffffffffu, ss, off);

    __shared__ float warp_ss[8];
    __shared__ float s_scale;
    int lane = tid & 31, wid = tid >> 5;
    if (lane == 0) warp_ss[wid] = ss;
    __syncthreads();
    if (tid == 0) {
        float tot = 0.f;
        #pragma unroll
        for (int i = 0; i < 8; i++) tot += warp_ss[i];
        s_scale = rsqrtf(tot / (float)HID + EPS);
    }
    __syncthreads();
    float scale = s_scale;

    float4 w0 = wr[tid];
    float4 w1 = wr[tid + 256];
    orow[2*tid]       = __floats2half2_rn(v0.x * scale * w0.x, v0.y * scale * w0.y);
    orow[2*tid + 1]   = __floats2half2_rn(v0.z * scale * w0.z, v0.w * scale * w0.w);
    orow[2*tid + 512] = __floats2half2_rn(v1.x * scale * w1.x, v1.y * scale * w1.y);
    orow[2*tid + 513] = __floats2half2_rn(v1.z * scale * w1.z, v1.w * scale * w1.w);
}

// ---------------- fp32 -> fp16(RNE) elementwise ----------------
__global__ __launch_bounds__(256) void to_f16_kernel(
    const float4* __restrict__ s, uint2* __restrict__ d, long n4)
{
    long i = (long)blockIdx.x * blockDim.x + threadIdx.x;
    long stride = (long)gridDim.x * blockDim.x;
    for (; i < n4; i += stride) {
        float4 v = s[i];
        __half2 lo = __floats2half2_rn(v.x, v.y);
        __half2 hi = __floats2half2_rn(v.z, v.w);
        uint2 o;
        o.x = *(uint32_t*)&lo;
        o.y = *(uint32_t*)&hi;
        d[i] = o;
    }
}

// ---------------- Wqo prep: Wq -> fp16 transposed, Wo -> fp16, one kernel ----------------
__global__ __launch_bounds__(256) void prep_wqo_kernel(
    const float* __restrict__ Wq, const float* __restrict__ Wo,
    __half* __restrict__ WqT, __half* __restrict__ WoH)
{
    __shared__ float tile[32][33];
    int x = blockIdx.x * 32 + threadIdx.x;   // src col
    int y0 = blockIdx.y * 32 + threadIdx.y;  // src row
    #pragma unroll
    for (int i = 0; i < 32; i += 8) {
        size_t idx = (size_t)(y0 + i) * HID + x;
        tile[threadIdx.y + i][threadIdx.x] = Wq[idx];
        WoH[idx] = __float2half_rn(Wo[idx]);   // straight convert, coalesced
    }
    __syncthreads();
    int tx = blockIdx.y * 32 + threadIdx.x;  // dst col (= src row)
    int ty = blockIdx.x * 32 + threadIdx.y;  // dst row (= src col)
    #pragma unroll
    for (int i = 0; i < 32; i += 8)
        WqT[(size_t)(ty + i) * HID + tx] = __float2half_rn(tile[threadIdx.x][threadIdx.y + i]);
}

// ---------------- plain GEMM: C[M,N] = A @ W^T (+R), mma.sync fp16 ----------------
// CTA tile 128x256, BK=64, 4-slot/3-inflight cp.async, single sync per iter,
// 16 warps (4M x 4N), warp tile 32x64, kk-level fragment double buffering.
// EPI 0: C(half) = rn(A@W^T);  EPI 1: C(float) = R + A@W^T
template<int EPI>
__global__ __launch_bounds__(NTHREADS, 1) void gemm_mma(
    const __half* __restrict__ A, const __half* __restrict__ W,
    const float* __restrict__ R, void* __restrict__ Cv, int K, int N)
{
    extern __shared__ __align__(1024) char smem[];
    uint32_t sb = s2u(smem);
    int tid = threadIdx.x;
    int lane = tid & 31, w = tid >> 5;
    int wm = w >> 2;      // 0..3  (32-row slice)
    int wn = w & 3;       // 0..3  (64-col slice)
    size_t row0 = (size_t)blockIdx.x * 128;
    size_t col0 = (size_t)blockIdx.y * 256;
    const int NK = K / BK;

    const __half* Abase = A + row0 * (size_t)K;
    const __half* Wbase = W + col0 * (size_t)K;

    auto load_stage = [&](int slot, int j) {
        uint32_t ab = sb + (uint32_t)slot * STAGE_B;
        uint32_t bb = ab + 16384;
        int kt = j * BK;
        #pragma unroll
        for (int p = 0; p < 2; p++) {
            int idx = p * NTHREADS + tid;
            int r = idx >> 3, c = idx & 7;   // 8 x 16B chunks per 128B row
            cpa16(ab + sw128((r << 7) + (c << 4)),
                  (const char*)(Abase + (size_t)r * K + kt) + (c << 4));
        }
        #pragma unroll
        for (int p = 0; p < 4; p++) {
            int idx = p * NTHREADS + tid;
            int r = idx >> 3, c = idx & 7;
            cpa16(bb + sw128((r << 7) + (c << 4)),
                  (const char*)(Wbase + (size_t)r * K + kt) + (c << 4));
        }
    };

    auto load_afr = [&](uint32_t ab, int kk, uint32_t af[2][4]) {
        #pragma unroll
        for (int mi = 0; mi < 2; mi++) {
            uint32_t off = (uint32_t)((wm * 32 + mi * 16 + (lane & 15)) << 7)
                         + (uint32_t)((kk << 5) + ((lane >> 4) << 4));
            ldsm4(af[mi][0], af[mi][1], af[mi][2], af[mi][3], ab + sw128(off));
        }
    };
    auto load_bfr = [&](uint32_t bb, int kk, uint32_t bf[8][2]) {
        #pragma unroll
        for (int bi = 0; bi < 4; bi++) {
            uint32_t off = (uint32_t)((wn * 64 + bi * 16 + ((lane >> 4) << 3) + (lane & 7)) << 7)
                         + (uint32_t)((kk << 5) + (((lane >> 3) & 1) << 4));
            ldsm4(bf[2*bi][0], bf[2*bi][1], bf[2*bi+1][0], bf[2*bi+1][1], bb + sw128(off));
        }
    };

    float acc[2][8][4];
    #pragma unroll
    for (int i = 0; i < 2; i++)
        #pragma unroll
        for (int jx = 0; jx < 8; jx++)
            #pragma unroll
            for (int e = 0; e < 4; e++) acc[i][jx][e] = 0.f;

    #pragma unroll
    for (int p = 0; p < STAGES - 1; p++) {
        load_stage(p, p);
        asm volatile("cp.async.commit_group;");
    }

    for (int j = 0; j < NK; j++) {
        asm volatile("cp.async.wait_group %0;" :: "n"(STAGES - 2));
        __syncthreads();
        if (j + STAGES - 1 < NK) load_stage((j + STAGES - 1) & 3, j + STAGES - 1);
        asm volatile("cp.async.commit_group;");

        int slot = j & 3;
        uint32_t ab = sb + (uint32_t)slot * STAGE_B;
        uint32_t bb = ab + 16384;

        uint32_t afr[2][2][4], bfr[2][8][2];
        load_afr(ab, 0, afr[0]);
        load_bfr(bb, 0, bfr[0]);
        #pragma unroll
        for (int kk = 0; kk < 4; kk++) {
            if (kk < 3) {
                load_afr(ab, kk + 1, afr[(kk + 1) & 1]);
                load_bfr(bb, kk + 1, bfr[(kk + 1) & 1]);
            }
            #pragma unroll
            for (int mi = 0; mi < 2; mi++)
                #pragma unroll
                for (int nj = 0; nj < 8; nj++)
                    mma_f16(acc[mi][nj], afr[kk & 1][mi], bfr[kk & 1][nj][0], bfr[kk & 1][nj][1]);
        }
        __syncthreads();
    }

    #pragma unroll
    for (int mi = 0; mi < 2; mi++) {
        size_t r = row0 + wm * 32 + mi * 16 + (lane >> 2);
        #pragma unroll
        for (int nj = 0; nj < 8; nj++) {
            size_t c = col0 + wn * 64 + nj * 8 + 2 * (lane & 3);
            if (EPI == 1) {
                float* C = (float*)Cv;
                const float2 r0 = *(const float2*)(R + r * (size_t)N + c);
                const float2 r1 = *(const float2*)(R + (r + 8) * (size_t)N + c);
                float2 v0 = make_float2(acc[mi][nj][0] + r0.x, acc[mi][nj][1] + r0.y);
                float2 v1 = make_float2(acc[mi][nj][2] + r1.x, acc[mi][nj][3] + r1.y);
                *(float2*)(C + r * (size_t)N + c) = v0;
                *(float2*)(C + (r + 8) * (size_t)N + c) = v1;
            } else {
                __half2* C = (__half2*)Cv;
                C[(r * (size_t)N + c) >> 1]       = __floats2half2_rn(acc[mi][nj][0], acc[mi][nj][1]);
                C[((r + 8) * (size_t)N + c) >> 1] = __floats2half2_rn(acc[mi][nj][2], acc[mi][nj][3]);
            }
        }
    }
}

// ---------------- fused gate/up GEMM: act(half) = rn(silu(A@Wg^T) * (A@Wu^T)) ----------------
__global__ __launch_bounds__(NTHREADS, 1) void gemm_gateup_mma(
    const __half* __restrict__ A, const __half* __restrict__ Wg,
    const __half* __restrict__ Wu, __half* __restrict__ C, int K, int N)
{
    extern __shared__ __align__(1024) char smem[];
    uint32_t sb = s2u(smem);
    int tid = threadIdx.x;
    int lane = tid & 31, w = tid >> 5;
    int wm = w >> 2;      // 0..3 (32-row slice)
    int wn = w & 3;       // 0..3 (32-col slice)
    size_t row0 = (size_t)blockIdx.x * 128;
    size_t col0 = (size_t)blockIdx.y * 128;
    const int NK = K / BK;

    const __half* Abase = A + row0 * (size_t)K;
    const __half* Gbase = Wg + col0 * (size_t)K;
    const __half* Ubase = Wu + col0 * (size_t)K;
    int nvalid = (int)((size_t)N - col0 < 128 ? (size_t)N - col0 : 128);

    auto load_stage = [&](int slot, int j) {
        uint32_t ab = sb + (uint32_t)slot * STAGE_B;
        uint32_t gb = ab + 16384;
        uint32_t ub = gb + 16384;
        int kt = j * BK;
        #pragma unroll
        for (int p = 0; p < 2; p++) {
            int idx = p * NTHREADS + tid;
            int r = idx >> 3, c = idx & 7;
            cpa16(ab + sw128((r << 7) + (c << 4)),
                  (const char*)(Abase + (size_t)r * K + kt) + (c << 4));
        }
        #pragma unroll
        for (int p = 0; p < 2; p++) {
            int idx = p * NTHREADS + tid;
            int r = idx >> 3, c = idx & 7;
            if (r < nvalid) {
                uint32_t swo = sw128((r << 7) + (c << 4));
                cpa16(gb + swo, (const char*)(Gbase + (size_t)r * K + kt) + (c << 4));
                cpa16(ub + swo, (const char*)(Ubase + (size_t)r * K + kt) + (c << 4));
            }
        }
    };

    auto load_afr = [&](uint32_t ab, int kk, uint32_t af[2][4]) {
        #pragma unroll
        for (int mi = 0; mi < 2; mi++) {
            uint32_t off = (uint32_t)((wm * 32 + mi * 16 + (lane & 15)) << 7)
                         + (uint32_t)((kk << 5) + ((lane >> 4) << 4));
            ldsm4(af[mi][0], af[mi][1], af[mi][2], af[mi][3], ab + sw128(off));
        }
    };
    auto load_wfr = [&](uint32_t wb, int kk, uint32_t wf[4][2]) {
        #pragma unroll
        for (int bi = 0; bi < 2; bi++) {
            uint32_t off = (uint32_t)((wn * 32 + bi * 16 + ((lane >> 4) << 3) + (lane & 7)) << 7)
                         + (uint32_t)((kk << 5) + (((lane >> 3) & 1) << 4));
            ldsm4(wf[2*bi][0], wf[2*bi][1], wf[2*bi+1][0], wf[2*bi+1][1], wb + sw128(off));
        }
    };

    float accg[2][4][4], accu[2][4][4];
    #pragma unroll
    for (int i = 0; i < 2; i++)
        #pragma unroll
        for (int jx = 0; jx < 4; jx++)
            #pragma unroll
            for (int e = 0; e < 4; e++) { accg[i][jx][e] = 0.f; accu[i][jx][e] = 0.f; }

    #pragma unroll
    for (int p = 0; p < STAGES - 1; p++) {
        load_stage(p, p);
        asm volatile("cp.async.commit_group;");
    }

    for (int j = 0; j < NK; j++) {
        asm volatile("cp.async.wait_group %0;" :: "n"(STAGES - 2));
        __syncthreads();
        if (j + STAGES - 1 < NK) load_stage((j + STAGES - 1) & 3, j + STAGES - 1);
        asm volatile("cp.async.commit_group;");

        int slot = j & 3;
        uint32_t ab = sb + (uint32_t)slot * STAGE_B;
        uint32_t gb = ab + 16384;
        uint32_t ub = gb + 16384;

        uint32_t afr[2][2][4], gfr[2][4][2], ufr[2][4][2];
        load_afr(ab, 0, afr[0]);
        load_wfr(gb, 0, gfr[0]);
        load_wfr(ub, 0, ufr[0]);
        #pragma unroll
        for (int kk = 0; kk < 4; kk++) {
            if (kk < 3) {
                load_afr(ab, kk + 1, afr[(kk + 1) & 1]);
                load_wfr(gb, kk + 1, gfr[(kk + 1) & 1]);
                load_wfr(ub, kk + 1, ufr[(kk + 1) & 1]);
            }
            #pragma unroll
            for (int mi = 0; mi < 2; mi++)
                #pragma unroll
                for (int nj = 0; nj < 4; nj++) {
                    mma_f16(accg[mi][nj], afr[kk & 1][mi], gfr[kk & 1][nj][0], gfr[kk & 1][nj][1]);
                    mma_f16(accu[mi][nj], afr[kk & 1][mi], ufr[kk & 1][nj][0], ufr[kk & 1][nj][1]);
                }
        }
        __syncthreads();
    }

    #pragma unroll
    for (int mi = 0; mi < 2; mi++) {
        size_t r = row0 + wm * 32 + mi * 16 + (lane >> 2);
        #pragma unroll
        for (int nj = 0; nj < 4; nj++) {
            size_t c = col0 + wn * 32 + nj * 8 + 2 * (lane & 3);
            if (c < (size_t)N) {
                __half2 v0 = __floats2half2_rn(fsilu(accg[mi][nj][0]) * accu[mi][nj][0],
                                               fsilu(accg[mi][nj][1]) * accu[mi][nj][1]);
                __half2 v1 = __floats2half2_rn(fsilu(accg[mi][nj][2]) * accu[mi][nj][2],
                                               fsilu(accg[mi][nj][3]) * accu[mi][nj][3]);
                *(__half2*)(C + r * (size_t)N + c) = v0;
                *(__half2*)(C + (r + 8) * (size_t)N + c) = v1;
            }
        }
    }
}

// ---------------- launch ----------------
extern "C" void kernel_launch(void* const* d_in, const int* in_sizes, int n_in,
                              void* d_out, int out_size)
{
    const float* x      = (const float*)d_in[0];
    const float* in_w   = (const float*)d_in[2];
    const float* post_w = (const float*)d_in[3];
    const float* Wq     = (const float*)d_in[4];
    const float* Wo     = (const float*)d_in[5];
    const float* Wg     = (const float*)d_in[6];
    const float* Wu     = (const float*)d_in[7];
    const float* Wd     = (const float*)d_in[8];
    float* out = (float*)d_out;

    __half *hnorm, *hpost, *act, *hWqT, *hWo, *hWqo, *hWg, *hWu, *hWd;
    float *hidden;
    cudaGetSymbolAddress((void**)&hnorm,  g_hnorm);
    cudaGetSymbolAddress((void**)&hidden, g_hidden);
    cudaGetSymbolAddress((void**)&hpost,  g_hpost);
    cudaGetSymbolAddress((void**)&act,    g_act);
    cudaGetSymbolAddress((void**)&hWqT,   g_hWqT);
    cudaGetSymbolAddress((void**)&hWo,    g_hWo);
    cudaGetSymbolAddress((void**)&hWqo,   g_hWqo);
    cudaGetSymbolAddress((void**)&hWg,    g_hWg);
    cudaGetSymbolAddress((void**)&hWu,    g_hWu);
    cudaGetSymbolAddress((void**)&hWd,    g_hWd);

    static cudaStream_t s2 = nullptr;
    static cudaEvent_t ev_fork = nullptr, ev_wqo = nullptr, ev_join = nullptr;
    if (s2 == nullptr) {
        cudaStreamCreateWithFlags(&s2, cudaStreamNonBlocking);
        cudaEventCreateWithFlags(&ev_fork, cudaEventDisableTiming);
        cudaEventCreateWithFlags(&ev_wqo,  cudaEventDisableTiming);
        cudaEventCreateWithFlags(&ev_join, cudaEventDisableTiming);
        cudaFuncSetAttribute(gemm_mma<0>, cudaFuncAttributeMaxDynamicSharedMemorySize, SMEM_TOTAL);
        cudaFuncSetAttribute(gemm_mma<1>, cudaFuncAttributeMaxDynamicSharedMemorySize, SMEM_TOTAL);
        cudaFuncSetAttribute(gemm_gateup_mma, cudaFuncAttributeMaxDynamicSharedMemorySize, SMEM_TOTAL);
    }

    const int CB = 1184;

    // ---- fork: Wqo chain first on s2 (it heads the critical path), then big converts ----
    cudaEventRecord(ev_fork, 0);
    cudaStreamWaitEvent(s2, ev_fork, 0);
    // Wq -> fp16 transposed AND Wo -> fp16, single kernel
    prep_wqo_kernel<<<dim3(HID/32, HID/32), dim3(32, 8), 0, s2>>>(Wq, Wo, hWqT, hWo);
    // Wqo = rn16(Wo @ Wq):  C[i,j] = sum_q Wo[i,q] * WqT[j,q]
    gemm_mma<0><<<dim3(HID/128, HID/256), NTHREADS, SMEM_TOTAL, s2>>>(hWo, hWqT, nullptr, hWqo, HID, HID);
    cudaEventRecord(ev_wqo, s2);
    // big MLP weight converts (overlap the hidden GEMM on the main stream)
    to_f16_kernel<<<CB, 256, 0, s2>>>((const float4*)Wg, (uint2*)hWg, (long)INTERD * HID / 4);
    to_f16_kernel<<<CB, 256, 0, s2>>>((const float4*)Wu, (uint2*)hWu, (long)INTERD * HID / 4);
    to_f16_kernel<<<CB, 256, 0, s2>>>((const float4*)Wd, (uint2*)hWd, (long)HID * INTERD / 4);
    cudaEventRecord(ev_join, s2);

    // ---- main stream ----
    // 1. h_norm = rn(rmsnorm(x) * in_w)   (concurrent with the Wqo chain)
    rmsnorm_kernel<<<T_TOK, 256>>>(x, in_w, hnorm);
    cudaStreamWaitEvent(0, ev_wqo, 0);
    // 2+3 fused. hidden = x + h_norm @ Wqo^T
    gemm_mma<1><<<dim3(T_TOK/128, HID/256), NTHREADS, SMEM_TOTAL>>>(hnorm, hWqo, x, hidden, HID, HID);
    // 4. h_post = rn(rmsnorm(hidden) * post_w)
    rmsnorm_kernel<<<T_TOK, 256>>>(hidden, post_w, hpost);
    // join: MLP weight converts must be done
    cudaStreamWaitEvent(0, ev_join, 0);
    // 5. act = rn(silu(h_post @ Wg^T) * (h_post @ Wu^T))   [86 tiles, last ragged 64]
    gemm_gateup_mma<<<dim3(T_TOK/128, (INTERD + 127)/128), NTHREADS, SMEM_TOTAL>>>(hpost, hWg, hWu, act, HID, INTERD);
    // 6. out = hidden + act @ Wd^T
    gemm_mma<1><<<dim3(T_TOK/128, HID/256), NTHREADS, SMEM_TOTAL>>>(act, hWd, hidden, out, INTERD, HID);
}